// round 2
// baseline (speedup 1.0000x reference)
#include <cuda_runtime.h>
#include <math.h>

#define SEQ 2048
#define HID 1024
#define NH 16
#define HD 64
#define CHUNK 64
#define NCHUNK (SEQ / CHUNK)

// ---------------- scratch (no allocations allowed) ----------------
__device__ float g_q[SEQ * HID];
__device__ float g_k[SEQ * HID];
__device__ float g_v[SEQ * HID];
__device__ float g_att[SEQ * HID];
__device__ float g_S[NH * NCHUNK * HD * HD];   // per-chunk K^T V, then exclusive prefix
__device__ float g_Z[NH * NCHUNK * HD];        // per-chunk sum of k, then exclusive prefix

// ---------------- GEMM: C[m][n] = sum_k A[m][k] * B[n][k] ----------------
// A: [M,K] row-major, B: [N,K] row-major (i.e. x @ W^T with W row-major)
#define BM 128
#define BN 128
#define BK 16

__global__ __launch_bounds__(256) void gemm_xwt_kernel(
    const float* __restrict__ A, const float* __restrict__ B,
    float* __restrict__ C, int K, int N, int act)
{
    __shared__ float As[BK][BM + 4];
    __shared__ float Bs[BK][BN + 4];

    const int tid = threadIdx.x;
    const int m0 = blockIdx.y * BM;
    const int n0 = blockIdx.x * BN;
    const int tx = tid & 15;   // 16 threads over N
    const int ty = tid >> 4;   // 16 threads over M

    float acc[8][8];
#pragma unroll
    for (int i = 0; i < 8; i++)
#pragma unroll
        for (int j = 0; j < 8; j++) acc[i][j] = 0.f;

    const int lr = tid >> 2;   // 0..63 row within tile
    const int lc = tid & 3;    // float4 column within BK=16

    const float* Aptr = A + (size_t)(m0 + lr) * K + lc * 4;
    const float* Bptr = B + (size_t)(n0 + lr) * K + lc * 4;

    for (int k0 = 0; k0 < K; k0 += BK) {
#pragma unroll
        for (int p = 0; p < 2; p++) {
            const int r = lr + p * 64;
            float4 va = *(const float4*)(Aptr + (size_t)(p * 64) * K + k0);
            As[lc * 4 + 0][r] = va.x; As[lc * 4 + 1][r] = va.y;
            As[lc * 4 + 2][r] = va.z; As[lc * 4 + 3][r] = va.w;
            float4 vb = *(const float4*)(Bptr + (size_t)(p * 64) * K + k0);
            Bs[lc * 4 + 0][r] = vb.x; Bs[lc * 4 + 1][r] = vb.y;
            Bs[lc * 4 + 2][r] = vb.z; Bs[lc * 4 + 3][r] = vb.w;
        }
        __syncthreads();
#pragma unroll
        for (int k = 0; k < BK; k++) {
            float af[8], bf[8];
#pragma unroll
            for (int i = 0; i < 8; i++) af[i] = As[k][ty * 8 + i];
#pragma unroll
            for (int j = 0; j < 8; j++) bf[j] = Bs[k][tx * 8 + j];
#pragma unroll
            for (int i = 0; i < 8; i++)
#pragma unroll
                for (int j = 0; j < 8; j++) acc[i][j] = fmaf(af[i], bf[j], acc[i][j]);
        }
        __syncthreads();
    }

#pragma unroll
    for (int i = 0; i < 8; i++) {
        const int m = m0 + ty * 8 + i;
#pragma unroll
        for (int j = 0; j < 8; j++) {
            float y = acc[i][j];
            if (act) y = (y > 0.f) ? (y + 1.f) : expf(y);   // elu(y)+1
            C[(size_t)m * N + n0 + tx * 8 + j] = y;
        }
    }
}

// ---------------- Pass A: per-chunk K^T V and sum(k) ----------------
__global__ __launch_bounds__(256) void chunk_stats_kernel()
{
    const int c = blockIdx.x;
    const int h = blockIdx.y;
    __shared__ float Ks[CHUNK][HD];
    __shared__ float Vs[CHUNK][HD];

    const int tid = threadIdx.x;
    const int t0 = c * CHUNK;
    const int lr = tid >> 4;   // 0..15
    const int lc = tid & 15;   // float4 col

#pragma unroll
    for (int p = 0; p < 4; p++) {
        const int t = lr + p * 16;
        *(float4*)&Ks[t][lc * 4] =
            *(const float4*)&g_k[(size_t)(t0 + t) * HID + h * HD + lc * 4];
        *(float4*)&Vs[t][lc * 4] =
            *(const float4*)&g_v[(size_t)(t0 + t) * HID + h * HD + lc * 4];
    }
    __syncthreads();

    const int tx = tid & 15, ty = tid >> 4;
    const int e0 = tx * 4, d0 = ty * 4;
    float acc[4][4];
#pragma unroll
    for (int i = 0; i < 4; i++)
#pragma unroll
        for (int j = 0; j < 4; j++) acc[i][j] = 0.f;

    for (int t = 0; t < CHUNK; t++) {
        float kf[4], vf[4];
#pragma unroll
        for (int i = 0; i < 4; i++) kf[i] = Ks[t][d0 + i];
#pragma unroll
        for (int j = 0; j < 4; j++) vf[j] = Vs[t][e0 + j];
#pragma unroll
        for (int i = 0; i < 4; i++)
#pragma unroll
            for (int j = 0; j < 4; j++) acc[i][j] = fmaf(kf[i], vf[j], acc[i][j]);
    }

    float* Sout = g_S + (size_t)(h * NCHUNK + c) * HD * HD;
#pragma unroll
    for (int i = 0; i < 4; i++)
#pragma unroll
        for (int j = 0; j < 4; j++) Sout[(d0 + i) * HD + e0 + j] = acc[i][j];

    if (tid < HD) {
        float z = 0.f;
        for (int t = 0; t < CHUNK; t++) z += Ks[t][tid];
        g_Z[(size_t)(h * NCHUNK + c) * HD + tid] = z;
    }
}

// ---------------- Pass B: in-place exclusive scan over chunks ----------------
__global__ __launch_bounds__(256) void chunk_scan_kernel()
{
    const int h = blockIdx.x;
    const int tid = threadIdx.x;
    float acc[16];
#pragma unroll
    for (int i = 0; i < 16; i++) acc[i] = 0.f;

    float* Sh = g_S + (size_t)h * NCHUNK * HD * HD;
    for (int c = 0; c < NCHUNK; c++) {
        float* p = Sh + (size_t)c * HD * HD;
#pragma unroll
        for (int i = 0; i < 16; i++) {
            const int e = i * 256 + tid;
            const float v = p[e];
            p[e] = acc[i];
            acc[i] += v;
        }
    }
    if (tid < HD) {
        float az = 0.f;
        float* Zh = g_Z + (size_t)h * NCHUNK * HD;
        for (int c = 0; c < NCHUNK; c++) {
            const float v = Zh[c * HD + tid];
            Zh[c * HD + tid] = az;
            az += v;
        }
    }
}

// ---------------- Pass C: per-chunk output ----------------
// O[t] = q_t @ S_prev + sum_{s<=t} (q_t . k_s) v_s ; denom = q_t.z_prev + rowsum
extern __shared__ float sm_c[];
__global__ __launch_bounds__(256) void chunk_out_kernel()
{
    const int c = blockIdx.x;
    const int h = blockIdx.y;
    float* Qs  = sm_c;            // 64*64
    float* KVs = sm_c + 4096;     // K first, then V
    float* Sp  = sm_c + 8192;     // prefix state
    float* Am  = sm_c + 12288;    // masked QK^T
    __shared__ float zprev[HD];
    __shared__ float dinv[CHUNK];

    const int tid = threadIdx.x;
    const int t0 = c * CHUNK;
    const int lr = tid >> 4;
    const int lc = tid & 15;

#pragma unroll
    for (int p = 0; p < 4; p++) {
        const int t = lr + p * 16;
        *(float4*)&Qs[t * HD + lc * 4] =
            *(const float4*)&g_q[(size_t)(t0 + t) * HID + h * HD + lc * 4];
        *(float4*)&KVs[t * HD + lc * 4] =
            *(const float4*)&g_k[(size_t)(t0 + t) * HID + h * HD + lc * 4];
    }
    {
        const float* Sg = g_S + (size_t)(h * NCHUNK + c) * HD * HD;
#pragma unroll
        for (int i = 0; i < 16; i++) {
            const int e = i * 256 + tid;
            Sp[e] = Sg[e];
        }
    }
    if (tid < HD) zprev[tid] = g_Z[(size_t)(h * NCHUNK + c) * HD + tid];
    __syncthreads();

    const int tx = tid & 15, ty = tid >> 4;
    const int trow = ty * 4, scol = tx * 4;

    // A = tril(Q K^T)
    float a[4][4];
#pragma unroll
    for (int i = 0; i < 4; i++)
#pragma unroll
        for (int j = 0; j < 4; j++) a[i][j] = 0.f;
    for (int d = 0; d < HD; d++) {
        float qf[4], kf[4];
#pragma unroll
        for (int i = 0; i < 4; i++) qf[i] = Qs[(trow + i) * HD + d];
#pragma unroll
        for (int j = 0; j < 4; j++) kf[j] = KVs[(scol + j) * HD + d];
#pragma unroll
        for (int i = 0; i < 4; i++)
#pragma unroll
            for (int j = 0; j < 4; j++) a[i][j] = fmaf(qf[i], kf[j], a[i][j]);
    }
#pragma unroll
    for (int i = 0; i < 4; i++)
#pragma unroll
        for (int j = 0; j < 4; j++)
            Am[(trow + i) * CHUNK + scol + j] = (scol + j <= trow + i) ? a[i][j] : 0.f;
    __syncthreads();

    // overwrite K buffer with V
#pragma unroll
    for (int p = 0; p < 4; p++) {
        const int t = lr + p * 16;
        *(float4*)&KVs[t * HD + lc * 4] =
            *(const float4*)&g_v[(size_t)(t0 + t) * HID + h * HD + lc * 4];
    }
    // denominator
    if (tid < CHUNK) {
        float rs = 0.f;
        for (int s = 0; s < CHUNK; s++) rs += Am[tid * CHUNK + s];
        float qz = 0.f;
        for (int d = 0; d < HD; d++) qz = fmaf(Qs[tid * HD + d], zprev[d], qz);
        dinv[tid] = 1.f / fmaxf(rs + qz, 1e-6f);
    }
    __syncthreads();

    // O = Q @ Sp + Am @ V
    const int e0 = tx * 4;
    float o[4][4];
#pragma unroll
    for (int i = 0; i < 4; i++)
#pragma unroll
        for (int j = 0; j < 4; j++) o[i][j] = 0.f;
    for (int d = 0; d < HD; d++) {
        float qf[4], sf[4];
#pragma unroll
        for (int i = 0; i < 4; i++) qf[i] = Qs[(trow + i) * HD + d];
#pragma unroll
        for (int j = 0; j < 4; j++) sf[j] = Sp[d * HD + e0 + j];
#pragma unroll
        for (int i = 0; i < 4; i++)
#pragma unroll
            for (int j = 0; j < 4; j++) o[i][j] = fmaf(qf[i], sf[j], o[i][j]);
    }
    for (int s = 0; s < CHUNK; s++) {
        float af[4], vf[4];
#pragma unroll
        for (int i = 0; i < 4; i++) af[i] = Am[(trow + i) * CHUNK + s];
#pragma unroll
        for (int j = 0; j < 4; j++) vf[j] = KVs[s * HD + e0 + j];
#pragma unroll
        for (int i = 0; i < 4; i++)
#pragma unroll
            for (int j = 0; j < 4; j++) o[i][j] = fmaf(af[i], vf[j], o[i][j]);
    }
#pragma unroll
    for (int i = 0; i < 4; i++) {
        const float di = dinv[trow + i];
#pragma unroll
        for (int j = 0; j < 4; j++)
            g_att[(size_t)(t0 + trow + i) * HID + h * HD + e0 + j] = o[i][j] * di;
    }
}

// ---------------- launch ----------------
extern "C" void kernel_launch(void* const* d_in, const int* in_sizes, int n_in,
                              void* d_out, int out_size)
{
    const float* x  = (const float*)d_in[0];
    const float* Wq = (const float*)d_in[1];
    const float* Wk = (const float*)d_in[2];
    const float* Wv = (const float*)d_in[3];
    const float* Wo = (const float*)d_in[4];
    float* out = (float*)d_out;

    float *q, *k, *v, *att;
    cudaGetSymbolAddress((void**)&q,   g_q);
    cudaGetSymbolAddress((void**)&k,   g_k);
    cudaGetSymbolAddress((void**)&v,   g_v);
    cudaGetSymbolAddress((void**)&att, g_att);

    static int smem_set = 0;
    if (!smem_set) {
        cudaFuncSetAttribute(chunk_out_kernel,
                             cudaFuncAttributeMaxDynamicSharedMemorySize,
                             4 * 4096 * (int)sizeof(float));
        smem_set = 1;
    }

    dim3 gg(HID / BN, SEQ / BM);
    gemm_xwt_kernel<<<gg, 256>>>(x, Wq, q, HID, HID, 1);  // q = elu(xWq^T)+1
    gemm_xwt_kernel<<<gg, 256>>>(x, Wk, k, HID, HID, 1);  // k = elu(xWk^T)+1
    gemm_xwt_kernel<<<gg, 256>>>(x, Wv, v, HID, HID, 0);  // v = xWv^T

    chunk_stats_kernel<<<dim3(NCHUNK, NH), 256>>>();
    chunk_scan_kernel<<<NH, 256>>>();
    chunk_out_kernel<<<dim3(NCHUNK, NH), 256, 4 * 4096 * sizeof(float)>>>();

    gemm_xwt_kernel<<<gg, 256>>>(att, Wo, out, HID, HID, 0);  // final projection
}

// round 4
// speedup vs baseline: 1.9764x; 1.9764x over previous
#include <cuda_runtime.h>
#include <math.h>
#include <stdint.h>

#define SEQ 2048
#define HID 1024
#define NH 16
#define HD 64
#define CHUNK 64
#define NCHUNK (SEQ / CHUNK)

// ---------------- scratch (no allocations allowed) ----------------
__device__ float g_q[SEQ * HID];
__device__ float g_k[SEQ * HID];
__device__ float g_v[SEQ * HID];
__device__ float g_att[SEQ * HID];
__device__ float g_S[NH * NCHUNK * HD * HD];   // per-chunk K^T V, then exclusive prefix
__device__ float g_Z[NH * NCHUNK * HD];        // per-chunk sum of k, then exclusive prefix

// ================= TF32 tensor-core GEMM: C[m][n] = sum_k A[m][k]*B[n][k] =================
// A: [M,K] row-major; B: [N,K] row-major (x @ W^T). M=SEQ, N=K=HID.
// mma.m16n8k8.row.col: A 16x8 row-major, B 8x8 col-major (= n-major, k-contiguous) — matches W directly.
#define GBM 128
#define GBN 64
#define GBK 32
#define GPAD 4   // smem row stride GBK+4=36 -> bank = 4*g + l4, conflict-free fragment loads

__device__ __forceinline__ uint32_t f2tf32(float f) {
    uint32_t u;
    asm("cvt.rna.tf32.f32 %0, %1;" : "=r"(u) : "f"(f));
    return u;
}

__global__ __launch_bounds__(256) void gemm_tf32_kernel(
    const float* __restrict__ A, const float* __restrict__ B,
    float* __restrict__ C, int act)
{
    __shared__ uint32_t As[GBM][GBK + GPAD];
    __shared__ uint32_t Bs[GBN][GBK + GPAD];

    const int tid = threadIdx.x;
    const int m0 = blockIdx.y * GBM;
    const int n0 = blockIdx.x * GBN;
    const int w    = tid >> 5;
    const int lane = tid & 31;
    const int g  = lane >> 2;   // 0..7
    const int l4 = lane & 3;    // 0..3
    const int wm = (w >> 1) * 32;   // warp M offset (4 warps over M)
    const int wn = (w & 1) * 32;    // warp N offset (2 warps over N)

    float c[2][4][4];
#pragma unroll
    for (int mi = 0; mi < 2; mi++)
#pragma unroll
        for (int ni = 0; ni < 4; ni++)
#pragma unroll
            for (int q = 0; q < 4; q++) c[mi][ni][q] = 0.f;

    const int lr = tid >> 3;        // 0..31
    const int lc = (tid & 7) * 4;   // 0,4,..,28

    for (int k0 = 0; k0 < HID; k0 += GBK) {
        // stage A tile (128 x 32), converting to tf32
#pragma unroll
        for (int p = 0; p < 4; p++) {
            const int r = lr + p * 32;
            float4 v = *(const float4*)&A[(size_t)(m0 + r) * HID + k0 + lc];
            As[r][lc + 0] = f2tf32(v.x);
            As[r][lc + 1] = f2tf32(v.y);
            As[r][lc + 2] = f2tf32(v.z);
            As[r][lc + 3] = f2tf32(v.w);
        }
        // stage B tile (64 x 32)
#pragma unroll
        for (int p = 0; p < 2; p++) {
            const int r = lr + p * 32;
            float4 v = *(const float4*)&B[(size_t)(n0 + r) * HID + k0 + lc];
            Bs[r][lc + 0] = f2tf32(v.x);
            Bs[r][lc + 1] = f2tf32(v.y);
            Bs[r][lc + 2] = f2tf32(v.z);
            Bs[r][lc + 3] = f2tf32(v.w);
        }
        __syncthreads();

#pragma unroll
        for (int kk = 0; kk < GBK; kk += 8) {
            uint32_t a[2][4], b[4][2];
#pragma unroll
            for (int mi = 0; mi < 2; mi++) {
                const int r = wm + mi * 16 + g;
                a[mi][0] = As[r    ][kk + l4];
                a[mi][1] = As[r + 8][kk + l4];
                a[mi][2] = As[r    ][kk + l4 + 4];
                a[mi][3] = As[r + 8][kk + l4 + 4];
            }
#pragma unroll
            for (int ni = 0; ni < 4; ni++) {
                const int r = wn + ni * 8 + g;
                b[ni][0] = Bs[r][kk + l4];
                b[ni][1] = Bs[r][kk + l4 + 4];
            }
#pragma unroll
            for (int mi = 0; mi < 2; mi++)
#pragma unroll
                for (int ni = 0; ni < 4; ni++)
                    asm volatile(
                        "mma.sync.aligned.m16n8k8.row.col.f32.tf32.tf32.f32 "
                        "{%0,%1,%2,%3}, {%4,%5,%6,%7}, {%8,%9}, {%0,%1,%2,%3};"
                        : "+f"(c[mi][ni][0]), "+f"(c[mi][ni][1]),
                          "+f"(c[mi][ni][2]), "+f"(c[mi][ni][3])
                        : "r"(a[mi][0]), "r"(a[mi][1]), "r"(a[mi][2]), "r"(a[mi][3]),
                          "r"(b[ni][0]), "r"(b[ni][1]));
        }
        __syncthreads();
    }

    // epilogue: optional elu(y)+1, vectorized float2 stores
#pragma unroll
    for (int mi = 0; mi < 2; mi++) {
#pragma unroll
        for (int ri = 0; ri < 2; ri++) {
            const int m = m0 + wm + mi * 16 + g + ri * 8;
#pragma unroll
            for (int ni = 0; ni < 4; ni++) {
                float y0 = c[mi][ni][ri * 2 + 0];
                float y1 = c[mi][ni][ri * 2 + 1];
                if (act) {
                    y0 = (y0 > 0.f) ? (y0 + 1.f) : expf(y0);
                    y1 = (y1 > 0.f) ? (y1 + 1.f) : expf(y1);
                }
                const int n = n0 + wn + ni * 8 + l4 * 2;
                *(float2*)&C[(size_t)m * HID + n] = make_float2(y0, y1);
            }
        }
    }
}

// ---------------- Pass A: per-chunk K^T V and sum(k) ----------------
__global__ __launch_bounds__(256) void chunk_stats_kernel()
{
    const int c = blockIdx.x;
    const int h = blockIdx.y;
    __shared__ float Ks[CHUNK][HD];
    __shared__ float Vs[CHUNK][HD];

    const int tid = threadIdx.x;
    const int t0 = c * CHUNK;
    const int lr = tid >> 4;
    const int lc = tid & 15;

#pragma unroll
    for (int p = 0; p < 4; p++) {
        const int t = lr + p * 16;
        *(float4*)&Ks[t][lc * 4] =
            *(const float4*)&g_k[(size_t)(t0 + t) * HID + h * HD + lc * 4];
        *(float4*)&Vs[t][lc * 4] =
            *(const float4*)&g_v[(size_t)(t0 + t) * HID + h * HD + lc * 4];
    }
    __syncthreads();

    const int tx = tid & 15, ty = tid >> 4;
    const int e0 = tx * 4, d0 = ty * 4;
    float acc[4][4];
#pragma unroll
    for (int i = 0; i < 4; i++)
#pragma unroll
        for (int j = 0; j < 4; j++) acc[i][j] = 0.f;

    for (int t = 0; t < CHUNK; t++) {
        float kf[4], vf[4];
#pragma unroll
        for (int i = 0; i < 4; i++) kf[i] = Ks[t][d0 + i];
#pragma unroll
        for (int j = 0; j < 4; j++) vf[j] = Vs[t][e0 + j];
#pragma unroll
        for (int i = 0; i < 4; i++)
#pragma unroll
            for (int j = 0; j < 4; j++) acc[i][j] = fmaf(kf[i], vf[j], acc[i][j]);
    }

    float* Sout = g_S + (size_t)(h * NCHUNK + c) * HD * HD;
#pragma unroll
    for (int i = 0; i < 4; i++)
#pragma unroll
        for (int j = 0; j < 4; j++) Sout[(d0 + i) * HD + e0 + j] = acc[i][j];

    if (tid < HD) {
        float z = 0.f;
        for (int t = 0; t < CHUNK; t++) z += Ks[t][tid];
        g_Z[(size_t)(h * NCHUNK + c) * HD + tid] = z;
    }
}

// ---------------- Pass B: in-place exclusive scan over chunks ----------------
__global__ __launch_bounds__(256) void chunk_scan_kernel()
{
    const int h = blockIdx.x;
    const int tid = threadIdx.x;
    float acc[16];
#pragma unroll
    for (int i = 0; i < 16; i++) acc[i] = 0.f;

    float* Sh = g_S + (size_t)h * NCHUNK * HD * HD;
    for (int c = 0; c < NCHUNK; c++) {
        float* p = Sh + (size_t)c * HD * HD;
#pragma unroll
        for (int i = 0; i < 16; i++) {
            const int e = i * 256 + tid;
            const float v = p[e];
            p[e] = acc[i];
            acc[i] += v;
        }
    }
    if (tid < HD) {
        float az = 0.f;
        float* Zh = g_Z + (size_t)h * NCHUNK * HD;
        for (int c = 0; c < NCHUNK; c++) {
            const float v = Zh[c * HD + tid];
            Zh[c * HD + tid] = az;
            az += v;
        }
    }
}

// ---------------- Pass C: per-chunk output ----------------
extern __shared__ float sm_c[];
__global__ __launch_bounds__(256) void chunk_out_kernel()
{
    const int c = blockIdx.x;
    const int h = blockIdx.y;
    float* Qs  = sm_c;            // 64*64
    float* KVs = sm_c + 4096;     // K first, then V
    float* Sp  = sm_c + 8192;     // prefix state
    float* Am  = sm_c + 12288;    // masked QK^T
    __shared__ float zprev[HD];
    __shared__ float dinv[CHUNK];

    const int tid = threadIdx.x;
    const int t0 = c * CHUNK;
    const int lr = tid >> 4;
    const int lc = tid & 15;

#pragma unroll
    for (int p = 0; p < 4; p++) {
        const int t = lr + p * 16;
        *(float4*)&Qs[t * HD + lc * 4] =
            *(const float4*)&g_q[(size_t)(t0 + t) * HID + h * HD + lc * 4];
        *(float4*)&KVs[t * HD + lc * 4] =
            *(const float4*)&g_k[(size_t)(t0 + t) * HID + h * HD + lc * 4];
    }
    {
        const float* Sg = g_S + (size_t)(h * NCHUNK + c) * HD * HD;
#pragma unroll
        for (int i = 0; i < 16; i++) {
            const int e = i * 256 + tid;
            Sp[e] = Sg[e];
        }
    }
    if (tid < HD) zprev[tid] = g_Z[(size_t)(h * NCHUNK + c) * HD + tid];
    __syncthreads();

    const int tx = tid & 15, ty = tid >> 4;
    const int trow = ty * 4, scol = tx * 4;

    // A = tril(Q K^T)
    float a[4][4];
#pragma unroll
    for (int i = 0; i < 4; i++)
#pragma unroll
        for (int j = 0; j < 4; j++) a[i][j] = 0.f;
    for (int d = 0; d < HD; d++) {
        float qf[4], kf[4];
#pragma unroll
        for (int i = 0; i < 4; i++) qf[i] = Qs[(trow + i) * HD + d];
#pragma unroll
        for (int j = 0; j < 4; j++) kf[j] = KVs[(scol + j) * HD + d];
#pragma unroll
        for (int i = 0; i < 4; i++)
#pragma unroll
            for (int j = 0; j < 4; j++) a[i][j] = fmaf(qf[i], kf[j], a[i][j]);
    }
#pragma unroll
    for (int i = 0; i < 4; i++)
#pragma unroll
        for (int j = 0; j < 4; j++)
            Am[(trow + i) * CHUNK + scol + j] = (scol + j <= trow + i) ? a[i][j] : 0.f;
    __syncthreads();

    // overwrite K buffer with V
#pragma unroll
    for (int p = 0; p < 4; p++) {
        const int t = lr + p * 16;
        *(float4*)&KVs[t * HD + lc * 4] =
            *(const float4*)&g_v[(size_t)(t0 + t) * HID + h * HD + lc * 4];
    }
    // denominator
    if (tid < CHUNK) {
        float rs = 0.f;
        for (int s = 0; s < CHUNK; s++) rs += Am[tid * CHUNK + s];
        float qz = 0.f;
        for (int d = 0; d < HD; d++) qz = fmaf(Qs[tid * HD + d], zprev[d], qz);
        dinv[tid] = 1.f / fmaxf(rs + qz, 1e-6f);
    }
    __syncthreads();

    // O = Q @ Sp + Am @ V
    const int e0 = tx * 4;
    float o[4][4];
#pragma unroll
    for (int i = 0; i < 4; i++)
#pragma unroll
        for (int j = 0; j < 4; j++) o[i][j] = 0.f;
    for (int d = 0; d < HD; d++) {
        float qf[4], sf[4];
#pragma unroll
        for (int i = 0; i < 4; i++) qf[i] = Qs[(trow + i) * HD + d];
#pragma unroll
        for (int j = 0; j < 4; j++) sf[j] = Sp[d * HD + e0 + j];
#pragma unroll
        for (int i = 0; i < 4; i++)
#pragma unroll
            for (int j = 0; j < 4; j++) o[i][j] = fmaf(qf[i], sf[j], o[i][j]);
    }
    for (int s = 0; s < CHUNK; s++) {
        float af[4], vf[4];
#pragma unroll
        for (int i = 0; i < 4; i++) af[i] = Am[(trow + i) * CHUNK + s];
#pragma unroll
        for (int j = 0; j < 4; j++) vf[j] = KVs[s * HD + e0 + j];
#pragma unroll
        for (int i = 0; i < 4; i++)
#pragma unroll
            for (int j = 0; j < 4; j++) o[i][j] = fmaf(af[i], vf[j], o[i][j]);
    }
#pragma unroll
    for (int i = 0; i < 4; i++) {
        const float di = dinv[trow + i];
#pragma unroll
        for (int j = 0; j < 4; j++)
            g_att[(size_t)(t0 + trow + i) * HID + h * HD + e0 + j] = o[i][j] * di;
    }
}

// ---------------- launch ----------------
extern "C" void kernel_launch(void* const* d_in, const int* in_sizes, int n_in,
                              void* d_out, int out_size)
{
    const float* x  = (const float*)d_in[0];
    const float* Wq = (const float*)d_in[1];
    const float* Wk = (const float*)d_in[2];
    const float* Wv = (const float*)d_in[3];
    const float* Wo = (const float*)d_in[4];
    float* out = (float*)d_out;

    float *q, *k, *v, *att;
    cudaGetSymbolAddress((void**)&q,   g_q);
    cudaGetSymbolAddress((void**)&k,   g_k);
    cudaGetSymbolAddress((void**)&v,   g_v);
    cudaGetSymbolAddress((void**)&att, g_att);

    static int smem_set = 0;
    if (!smem_set) {
        cudaFuncSetAttribute(chunk_out_kernel,
                             cudaFuncAttributeMaxDynamicSharedMemorySize,
                             4 * 4096 * (int)sizeof(float));
        smem_set = 1;
    }

    dim3 gg(HID / GBN, SEQ / GBM);   // 16 x 16 = 256 CTAs
    gemm_tf32_kernel<<<gg, 256>>>(x, Wq, q, 1);   // q = elu(xWq^T)+1
    gemm_tf32_kernel<<<gg, 256>>>(x, Wk, k, 1);   // k = elu(xWk^T)+1
    gemm_tf32_kernel<<<gg, 256>>>(x, Wv, v, 0);   // v = xWv^T

    chunk_stats_kernel<<<dim3(NCHUNK, NH), 256>>>();
    chunk_scan_kernel<<<NH, 256>>>();
    chunk_out_kernel<<<dim3(NCHUNK, NH), 256, 4 * 4096 * sizeof(float)>>>();

    gemm_tf32_kernel<<<gg, 256>>>(att, Wo, out, 0);  // final projection
}

// round 7
// speedup vs baseline: 2.1368x; 1.0812x over previous
#include <cuda_runtime.h>
#include <math.h>
#include <stdint.h>

#define SEQ 2048
#define HID 1024
#define NH 16
#define HD 64
#define CHUNK 64
#define NCHUNK (SEQ / CHUNK)

// ---------------- scratch (no allocations allowed) ----------------
__device__ float g_q[SEQ * HID];
__device__ float g_k[SEQ * HID];
__device__ float g_v[SEQ * HID];
__device__ float g_att[SEQ * HID];
__device__ float g_S[NH * NCHUNK * HD * HD];
__device__ float g_Z[NH * NCHUNK * HD];

__device__ __forceinline__ uint32_t f2tf32(float f) {
    uint32_t u;
    asm("cvt.rna.tf32.f32 %0, %1;" : "=r"(u) : "f"(f));
    return u;
}
__device__ __forceinline__ uint32_t smem_u32(const void* p) {
    uint32_t a;
    asm("{ .reg .u64 t; cvta.to.shared.u64 t, %1; cvt.u32.u64 %0, t; }" : "=r"(a) : "l"(p));
    return a;
}

// ================= pipelined tf32 mma.sync GEMM =================
// C[m][n] = sum_k A[m][k] * B[n][k]; A:[SEQ,HID] row-major, B:[HID,HID] row-major.
// CTA tile 128x128, BK=16, 3-stage cp.async pipeline, 8 warps (2M x 4N), warp tile 64x32.
#define GBK 16
#define GSTRIDE 20              // floats per smem row (16 + 4 pad)
#define NSTAGE (HID / GBK)      // 64
#define NBUF 3
#define TILE_FLOATS (128 * GSTRIDE)            // one operand tile
#define STAGE_FLOATS (2 * TILE_FLOATS)         // A + B
#define GEMM_SMEM (NBUF * STAGE_FLOATS * 4)    // 61440 bytes

__device__ __forceinline__ void cpasync16(uint32_t saddr, const float* gaddr) {
    asm volatile("cp.async.cg.shared.global [%0], [%1], 16;" :: "r"(saddr), "l"(gaddr));
}

struct GemmArgs { const float* A; const float* B; float* C; int act; };

__device__ __forceinline__ void gemm_body(const float* __restrict__ A,
                                          const float* __restrict__ B,
                                          float* __restrict__ C, int act,
                                          int m0, int n0, char* smem)
{
    const uint32_t sbase = smem_u32(smem);
    const int tid = threadIdx.x;
    const int w = tid >> 5;
    const int lane = tid & 31;
    const int g = lane >> 2;
    const int l4 = lane & 3;
    const int wm = (w >> 2) * 64;   // 2 warps over M
    const int wn = (w & 3) * 32;    // 4 warps over N

    // per-thread staging: 2 x 16B for A, 2 x 16B for B per stage
    const int idx0 = tid;          // 0..255
    const int idx1 = tid + 256;    // 256..511
    const int ar0 = idx0 >> 2, ak0 = (idx0 & 3) * 4;
    const int ar1 = idx1 >> 2, ak1 = (idx1 & 3) * 4;

    float c[4][4][4];
#pragma unroll
    for (int mi = 0; mi < 4; mi++)
#pragma unroll
        for (int ni = 0; ni < 4; ni++)
#pragma unroll
            for (int q = 0; q < 4; q++) c[mi][ni][q] = 0.f;

    auto prefetch = [&](int s) {
        const int b = s % NBUF;
        const uint32_t ab = sbase + (uint32_t)(b * STAGE_FLOATS) * 4;
        const uint32_t bb = ab + TILE_FLOATS * 4;
        const int k0 = s * GBK;
        cpasync16(ab + (ar0 * GSTRIDE + ak0) * 4, &A[(size_t)(m0 + ar0) * HID + k0 + ak0]);
        cpasync16(ab + (ar1 * GSTRIDE + ak1) * 4, &A[(size_t)(m0 + ar1) * HID + k0 + ak1]);
        cpasync16(bb + (ar0 * GSTRIDE + ak0) * 4, &B[(size_t)(n0 + ar0) * HID + k0 + ak0]);
        cpasync16(bb + (ar1 * GSTRIDE + ak1) * 4, &B[(size_t)(n0 + ar1) * HID + k0 + ak1]);
        asm volatile("cp.async.commit_group;" ::: "memory");
    };

    prefetch(0);
    prefetch(1);

    for (int s = 0; s < NSTAGE; s++) {
        asm volatile("cp.async.wait_group 1;" ::: "memory");
        __syncthreads();
        if (s + 2 < NSTAGE) prefetch(s + 2);

        const int b = s % NBUF;
        const float* As = (const float*)(smem) + b * STAGE_FLOATS;
        const float* Bs = As + TILE_FLOATS;

#pragma unroll
        for (int kk = 0; kk < GBK; kk += 8) {
            uint32_t a[4][4], bq[4][2];
#pragma unroll
            for (int mi = 0; mi < 4; mi++) {
                const int r = wm + mi * 16 + g;
                a[mi][0] = f2tf32(As[r * GSTRIDE + kk + l4]);
                a[mi][1] = f2tf32(As[(r + 8) * GSTRIDE + kk + l4]);
                a[mi][2] = f2tf32(As[r * GSTRIDE + kk + l4 + 4]);
                a[mi][3] = f2tf32(As[(r + 8) * GSTRIDE + kk + l4 + 4]);
            }
#pragma unroll
            for (int ni = 0; ni < 4; ni++) {
                const int r = wn + ni * 8 + g;
                bq[ni][0] = f2tf32(Bs[r * GSTRIDE + kk + l4]);
                bq[ni][1] = f2tf32(Bs[r * GSTRIDE + kk + l4 + 4]);
            }
#pragma unroll
            for (int mi = 0; mi < 4; mi++)
#pragma unroll
                for (int ni = 0; ni < 4; ni++)
                    asm volatile(
                        "mma.sync.aligned.m16n8k8.row.col.f32.tf32.tf32.f32 "
                        "{%0,%1,%2,%3}, {%4,%5,%6,%7}, {%8,%9}, {%0,%1,%2,%3};"
                        : "+f"(c[mi][ni][0]), "+f"(c[mi][ni][1]),
                          "+f"(c[mi][ni][2]), "+f"(c[mi][ni][3])
                        : "r"(a[mi][0]), "r"(a[mi][1]), "r"(a[mi][2]), "r"(a[mi][3]),
                          "r"(bq[ni][0]), "r"(bq[ni][1]));
        }
        __syncthreads();
    }
    asm volatile("cp.async.wait_group 0;" ::: "memory");

#pragma unroll
    for (int mi = 0; mi < 4; mi++) {
#pragma unroll
        for (int ri = 0; ri < 2; ri++) {
            const int m = m0 + wm + mi * 16 + g + ri * 8;
#pragma unroll
            for (int ni = 0; ni < 4; ni++) {
                float y0 = c[mi][ni][ri * 2 + 0];
                float y1 = c[mi][ni][ri * 2 + 1];
                if (act) {
                    y0 = (y0 > 0.f) ? (y0 + 1.f) : expf(y0);
                    y1 = (y1 > 0.f) ? (y1 + 1.f) : expf(y1);
                }
                const int n = n0 + wn + ni * 8 + l4 * 2;
                *(float2*)&C[(size_t)m * HID + n] = make_float2(y0, y1);
            }
        }
    }
}

// fused QKV: z selects weight/dest/activation
extern __shared__ char sm_g[];
__global__ __launch_bounds__(256, 2) void gemm_qkv_kernel(
    const float* __restrict__ x,
    const float* __restrict__ Wq, const float* __restrict__ Wk, const float* __restrict__ Wv)
{
    const int z = blockIdx.z;
    const float* W = (z == 0) ? Wq : (z == 1) ? Wk : Wv;
    float* dst = (z == 0) ? g_q : (z == 1) ? g_k : g_v;
    gemm_body(x, W, dst, z != 2, blockIdx.y * 128, blockIdx.x * 128, sm_g);
}

__global__ __launch_bounds__(256, 2) void gemm_out_kernel(
    const float* __restrict__ Wo, float* __restrict__ out)
{
    gemm_body(g_att, Wo, out, 0, blockIdx.y * 128, blockIdx.x * 128, sm_g);
}

// ---------------- Pass A: per-chunk K^T V and sum(k) ----------------
__global__ __launch_bounds__(256) void chunk_stats_kernel()
{
    const int c = blockIdx.x;
    const int h = blockIdx.y;
    __shared__ float Ks[CHUNK][HD];
    __shared__ float Vs[CHUNK][HD];

    const int tid = threadIdx.x;
    const int t0 = c * CHUNK;
    const int lr = tid >> 4;
    const int lc = tid & 15;

#pragma unroll
    for (int p = 0; p < 4; p++) {
        const int t = lr + p * 16;
        *(float4*)&Ks[t][lc * 4] =
            *(const float4*)&g_k[(size_t)(t0 + t) * HID + h * HD + lc * 4];
        *(float4*)&Vs[t][lc * 4] =
            *(const float4*)&g_v[(size_t)(t0 + t) * HID + h * HD + lc * 4];
    }
    __syncthreads();

    const int tx = tid & 15, ty = tid >> 4;
    const int e0 = tx * 4, d0 = ty * 4;
    float acc[4][4];
#pragma unroll
    for (int i = 0; i < 4; i++)
#pragma unroll
        for (int j = 0; j < 4; j++) acc[i][j] = 0.f;

    for (int t = 0; t < CHUNK; t++) {
        float kf[4], vf[4];
#pragma unroll
        for (int i = 0; i < 4; i++) kf[i] = Ks[t][d0 + i];
#pragma unroll
        for (int j = 0; j < 4; j++) vf[j] = Vs[t][e0 + j];
#pragma unroll
        for (int i = 0; i < 4; i++)
#pragma unroll
            for (int j = 0; j < 4; j++) acc[i][j] = fmaf(kf[i], vf[j], acc[i][j]);
    }

    float* Sout = g_S + (size_t)(h * NCHUNK + c) * HD * HD;
#pragma unroll
    for (int i = 0; i < 4; i++)
#pragma unroll
        for (int j = 0; j < 4; j++) Sout[(d0 + i) * HD + e0 + j] = acc[i][j];

    if (tid < HD) {
        float z = 0.f;
        for (int t = 0; t < CHUNK; t++) z += Ks[t][tid];
        g_Z[(size_t)(h * NCHUNK + c) * HD + tid] = z;
    }
}

// ---------------- Pass B: in-place exclusive scan over chunks ----------------
__global__ __launch_bounds__(256) void chunk_scan_kernel()
{
    const int h = blockIdx.x;
    const int tid = threadIdx.x;
    float acc[16];
#pragma unroll
    for (int i = 0; i < 16; i++) acc[i] = 0.f;

    float* Sh = g_S + (size_t)h * NCHUNK * HD * HD;
    for (int c = 0; c < NCHUNK; c++) {
        float* p = Sh + (size_t)c * HD * HD;
#pragma unroll
        for (int i = 0; i < 16; i++) {
            const int e = i * 256 + tid;
            const float v = p[e];
            p[e] = acc[i];
            acc[i] += v;
        }
    }
    if (tid < HD) {
        float az = 0.f;
        float* Zh = g_Z + (size_t)h * NCHUNK * HD;
        for (int c = 0; c < NCHUNK; c++) {
            const float v = Zh[c * HD + tid];
            Zh[c * HD + tid] = az;
            az += v;
        }
    }
}

// ---------------- Pass C: per-chunk output ----------------
extern __shared__ float sm_c[];
__global__ __launch_bounds__(256) void chunk_out_kernel()
{
    const int c = blockIdx.x;
    const int h = blockIdx.y;
    float* Qs  = sm_c;
    float* KVs = sm_c + 4096;
    float* Sp  = sm_c + 8192;
    float* Am  = sm_c + 12288;
    __shared__ float zprev[HD];
    __shared__ float dinv[CHUNK];

    const int tid = threadIdx.x;
    const int t0 = c * CHUNK;
    const int lr = tid >> 4;
    const int lc = tid & 15;

#pragma unroll
    for (int p = 0; p < 4; p++) {
        const int t = lr + p * 16;
        *(float4*)&Qs[t * HD + lc * 4] =
            *(const float4*)&g_q[(size_t)(t0 + t) * HID + h * HD + lc * 4];
        *(float4*)&KVs[t * HD + lc * 4] =
            *(const float4*)&g_k[(size_t)(t0 + t) * HID + h * HD + lc * 4];
    }
    {
        const float* Sg = g_S + (size_t)(h * NCHUNK + c) * HD * HD;
#pragma unroll
        for (int i = 0; i < 16; i++) {
            const int e = i * 256 + tid;
            Sp[e] = Sg[e];
        }
    }
    if (tid < HD) zprev[tid] = g_Z[(size_t)(h * NCHUNK + c) * HD + tid];
    __syncthreads();

    const int tx = tid & 15, ty = tid >> 4;
    const int trow = ty * 4, scol = tx * 4;

    float a[4][4];
#pragma unroll
    for (int i = 0; i < 4; i++)
#pragma unroll
        for (int j = 0; j < 4; j++) a[i][j] = 0.f;
    for (int d = 0; d < HD; d++) {
        float qf[4], kf[4];
#pragma unroll
        for (int i = 0; i < 4; i++) qf[i] = Qs[(trow + i) * HD + d];
#pragma unroll
        for (int j = 0; j < 4; j++) kf[j] = KVs[(scol + j) * HD + d];
#pragma unroll
        for (int i = 0; i < 4; i++)
#pragma unroll
            for (int j = 0; j < 4; j++) a[i][j] = fmaf(qf[i], kf[j], a[i][j]);
    }
#pragma unroll
    for (int i = 0; i < 4; i++)
#pragma unroll
        for (int j = 0; j < 4; j++)
            Am[(trow + i) * CHUNK + scol + j] = (scol + j <= trow + i) ? a[i][j] : 0.f;
    __syncthreads();

#pragma unroll
    for (int p = 0; p < 4; p++) {
        const int t = lr + p * 16;
        *(float4*)&KVs[t * HD + lc * 4] =
            *(const float4*)&g_v[(size_t)(t0 + t) * HID + h * HD + lc * 4];
    }
    if (tid < CHUNK) {
        float rs = 0.f;
        for (int s = 0; s < CHUNK; s++) rs += Am[tid * CHUNK + s];
        float qz = 0.f;
        for (int d = 0; d < HD; d++) qz = fmaf(Qs[tid * HD + d], zprev[d], qz);
        dinv[tid] = 1.f / fmaxf(rs + qz, 1e-6f);
    }
    __syncthreads();

    const int e0 = tx * 4;
    float o[4][4];
#pragma unroll
    for (int i = 0; i < 4; i++)
#pragma unroll
        for (int j = 0; j < 4; j++) o[i][j] = 0.f;
    for (int d = 0; d < HD; d++) {
        float qf[4], sf[4];
#pragma unroll
        for (int i = 0; i < 4; i++) qf[i] = Qs[(trow + i) * HD + d];
#pragma unroll
        for (int j = 0; j < 4; j++) sf[j] = Sp[d * HD + e0 + j];
#pragma unroll
        for (int i = 0; i < 4; i++)
#pragma unroll
            for (int j = 0; j < 4; j++) o[i][j] = fmaf(qf[i], sf[j], o[i][j]);
    }
    for (int s = 0; s < CHUNK; s++) {
        float af[4], vf[4];
#pragma unroll
        for (int i = 0; i < 4; i++) af[i] = Am[(trow + i) * CHUNK + s];
#pragma unroll
        for (int j = 0; j < 4; j++) vf[j] = KVs[s * HD + e0 + j];
#pragma unroll
        for (int i = 0; i < 4; i++)
#pragma unroll
            for (int j = 0; j < 4; j++) o[i][j] = fmaf(af[i], vf[j], o[i][j]);
    }
#pragma unroll
    for (int i = 0; i < 4; i++) {
        const float di = dinv[trow + i];
#pragma unroll
        for (int j = 0; j < 4; j++)
            g_att[(size_t)(t0 + trow + i) * HID + h * HD + e0 + j] = o[i][j] * di;
    }
}

// ---------------- launch ----------------
extern "C" void kernel_launch(void* const* d_in, const int* in_sizes, int n_in,
                              void* d_out, int out_size)
{
    const float* x  = (const float*)d_in[0];
    const float* Wq = (const float*)d_in[1];
    const float* Wk = (const float*)d_in[2];
    const float* Wv = (const float*)d_in[3];
    const float* Wo = (const float*)d_in[4];
    float* out = (float*)d_out;

    static int attr_set = 0;
    if (!attr_set) {
        cudaFuncSetAttribute(chunk_out_kernel,
                             cudaFuncAttributeMaxDynamicSharedMemorySize,
                             4 * 4096 * (int)sizeof(float));
        cudaFuncSetAttribute(gemm_qkv_kernel,
                             cudaFuncAttributeMaxDynamicSharedMemorySize, GEMM_SMEM);
        cudaFuncSetAttribute(gemm_out_kernel,
                             cudaFuncAttributeMaxDynamicSharedMemorySize, GEMM_SMEM);
        attr_set = 1;
    }

    dim3 gq(HID / 128, SEQ / 128, 3);   // 8 x 16 x 3 = 384 CTAs
    gemm_qkv_kernel<<<gq, 256, GEMM_SMEM>>>(x, Wq, Wk, Wv);

    chunk_stats_kernel<<<dim3(NCHUNK, NH), 256>>>();
    chunk_scan_kernel<<<NH, 256>>>();
    chunk_out_kernel<<<dim3(NCHUNK, NH), 256, 4 * 4096 * sizeof(float)>>>();

    dim3 go(HID / 128, SEQ / 128);
    gemm_out_kernel<<<go, 256, GEMM_SMEM>>>(Wo, out);
}

// round 8
// speedup vs baseline: 2.8549x; 1.3360x over previous
#include <cuda_runtime.h>
#include <math.h>
#include <stdint.h>

#define SEQ 2048
#define HID 1024
#define NH 16
#define HD 64
#define CHUNK 64
#define NCHUNK (SEQ / CHUNK)

// ---------------- scratch ----------------
__device__ float g_q[SEQ * HID];
__device__ float g_k[SEQ * HID];
__device__ float g_v[SEQ * HID];
__device__ float g_att[SEQ * HID];     // stored pre-rounded to tf32
__device__ float g_S[NH * NCHUNK * HD * HD];
__device__ float g_Z[NH * NCHUNK * HD];
// tf32-pre-rounded operands for the GEMMs
__device__ float g_xr[SEQ * HID];
__device__ float g_wqr[HID * HID];
__device__ float g_wkr[HID * HID];
__device__ float g_wvr[HID * HID];
__device__ float g_wor[HID * HID];

__device__ __forceinline__ uint32_t f2tf32(float f) {
    uint32_t u;
    asm("cvt.rna.tf32.f32 %0, %1;" : "=r"(u) : "f"(f));
    return u;
}
__device__ __forceinline__ float rndtf32(float f) {
    return __uint_as_float(f2tf32(f));
}
__device__ __forceinline__ uint32_t smem_u32(const void* p) {
    uint32_t a;
    asm("{ .reg .u64 t; cvta.to.shared.u64 t, %1; cvt.u32.u64 %0, t; }" : "=r"(a) : "l"(p));
    return a;
}

// ---------------- pre-round pass ----------------
__global__ __launch_bounds__(256) void round_kernel(const float* __restrict__ src,
                                                    float* __restrict__ dst, int n4)
{
    int i = blockIdx.x * blockDim.x + threadIdx.x;
    if (i < n4) {
        float4 v = ((const float4*)src)[i];
        v.x = rndtf32(v.x); v.y = rndtf32(v.y); v.z = rndtf32(v.z); v.w = rndtf32(v.w);
        ((float4*)dst)[i] = v;
    }
}

// ================= pipelined tf32 mma.sync GEMM (pre-rounded inputs) =================
// C[m][n] = sum_k A[m][k]*B[n][k]. CTA 128x128, BK=32, 3-stage cp.async, 8 warps 64x32.
#define GBK 32
#define GSTRIDE 36
#define NSTAGE (HID / GBK)      // 32
#define NBUF 3
#define TILE_FLOATS (128 * GSTRIDE)
#define STAGE_FLOATS (2 * TILE_FLOATS)
#define GEMM_SMEM (NBUF * STAGE_FLOATS * 4)   // 110592 B

__device__ __forceinline__ void cpasync16(uint32_t saddr, const float* gaddr) {
    asm volatile("cp.async.cg.shared.global [%0], [%1], 16;" :: "r"(saddr), "l"(gaddr));
}

__device__ __forceinline__ void gemm_body(const float* __restrict__ A,
                                          const float* __restrict__ B,
                                          float* __restrict__ C, int act,
                                          int m0, int n0, char* smem)
{
    const uint32_t sbase = smem_u32(smem);
    const int tid = threadIdx.x;
    const int w = tid >> 5;
    const int lane = tid & 31;
    const int g = lane >> 2;
    const int l4 = lane & 3;
    const int wm = (w >> 2) * 64;
    const int wn = (w & 3) * 32;

    float c[4][4][4];
#pragma unroll
    for (int mi = 0; mi < 4; mi++)
#pragma unroll
        for (int ni = 0; ni < 4; ni++)
#pragma unroll
            for (int q = 0; q < 4; q++) c[mi][ni][q] = 0.f;

    auto prefetch = [&](int s) {
        const int b = s % NBUF;
        const uint32_t ab = sbase + (uint32_t)(b * STAGE_FLOATS) * 4;
        const uint32_t bb = ab + TILE_FLOATS * 4;
        const int k0 = s * GBK;
#pragma unroll
        for (int p = 0; p < 4; p++) {
            const int idx = tid + p * 256;
            const int r = idx >> 3, kk = (idx & 7) * 4;
            cpasync16(ab + (r * GSTRIDE + kk) * 4, &A[(size_t)(m0 + r) * HID + k0 + kk]);
            cpasync16(bb + (r * GSTRIDE + kk) * 4, &B[(size_t)(n0 + r) * HID + k0 + kk]);
        }
        asm volatile("cp.async.commit_group;" ::: "memory");
    };

    prefetch(0);
    prefetch(1);

    for (int s = 0; s < NSTAGE; s++) {
        asm volatile("cp.async.wait_group 1;" ::: "memory");
        __syncthreads();
        if (s + 2 < NSTAGE) prefetch(s + 2);

        const int b = s % NBUF;
        const float* As = (const float*)(smem) + b * STAGE_FLOATS;
        const float* Bs = As + TILE_FLOATS;

#pragma unroll
        for (int kk = 0; kk < GBK; kk += 8) {
            uint32_t a[4][4], bq[4][2];
#pragma unroll
            for (int mi = 0; mi < 4; mi++) {
                const int r = wm + mi * 16 + g;
                a[mi][0] = __float_as_uint(As[r * GSTRIDE + kk + l4]);
                a[mi][1] = __float_as_uint(As[(r + 8) * GSTRIDE + kk + l4]);
                a[mi][2] = __float_as_uint(As[r * GSTRIDE + kk + l4 + 4]);
                a[mi][3] = __float_as_uint(As[(r + 8) * GSTRIDE + kk + l4 + 4]);
            }
#pragma unroll
            for (int ni = 0; ni < 4; ni++) {
                const int r = wn + ni * 8 + g;
                bq[ni][0] = __float_as_uint(Bs[r * GSTRIDE + kk + l4]);
                bq[ni][1] = __float_as_uint(Bs[r * GSTRIDE + kk + l4 + 4]);
            }
#pragma unroll
            for (int mi = 0; mi < 4; mi++)
#pragma unroll
                for (int ni = 0; ni < 4; ni++)
                    asm volatile(
                        "mma.sync.aligned.m16n8k8.row.col.f32.tf32.tf32.f32 "
                        "{%0,%1,%2,%3}, {%4,%5,%6,%7}, {%8,%9}, {%0,%1,%2,%3};"
                        : "+f"(c[mi][ni][0]), "+f"(c[mi][ni][1]),
                          "+f"(c[mi][ni][2]), "+f"(c[mi][ni][3])
                        : "r"(a[mi][0]), "r"(a[mi][1]), "r"(a[mi][2]), "r"(a[mi][3]),
                          "r"(bq[ni][0]), "r"(bq[ni][1]));
        }
        __syncthreads();
    }
    asm volatile("cp.async.wait_group 0;" ::: "memory");

#pragma unroll
    for (int mi = 0; mi < 4; mi++) {
#pragma unroll
        for (int ri = 0; ri < 2; ri++) {
            const int m = m0 + wm + mi * 16 + g + ri * 8;
#pragma unroll
            for (int ni = 0; ni < 4; ni++) {
                float y0 = c[mi][ni][ri * 2 + 0];
                float y1 = c[mi][ni][ri * 2 + 1];
                if (act) {
                    y0 = (y0 > 0.f) ? (y0 + 1.f) : expf(y0);
                    y1 = (y1 > 0.f) ? (y1 + 1.f) : expf(y1);
                }
                const int n = n0 + wn + ni * 8 + l4 * 2;
                *(float2*)&C[(size_t)m * HID + n] = make_float2(y0, y1);
            }
        }
    }
}

extern __shared__ char sm_g[];
__global__ __launch_bounds__(256, 2) void gemm_qkv_kernel()
{
    const int z = blockIdx.z;
    const float* W = (z == 0) ? g_wqr : (z == 1) ? g_wkr : g_wvr;
    float* dst = (z == 0) ? g_q : (z == 1) ? g_k : g_v;
    gemm_body(g_xr, W, dst, z != 2, blockIdx.y * 128, blockIdx.x * 128, sm_g);
}

__global__ __launch_bounds__(256, 2) void gemm_out_kernel(float* __restrict__ out)
{
    gemm_body(g_att, g_wor, out, 0, blockIdx.y * 128, blockIdx.x * 128, sm_g);
}

// ---------------- Pass A: per-chunk K^T V and sum(k) ----------------
__global__ __launch_bounds__(256) void chunk_stats_kernel()
{
    const int c = blockIdx.x;
    const int h = blockIdx.y;
    __shared__ float Ks[CHUNK][HD];
    __shared__ float Vs[CHUNK][HD];

    const int tid = threadIdx.x;
    const int t0 = c * CHUNK;
    const int lr = tid >> 4;
    const int lc = tid & 15;

#pragma unroll
    for (int p = 0; p < 4; p++) {
        const int t = lr + p * 16;
        *(float4*)&Ks[t][lc * 4] =
            *(const float4*)&g_k[(size_t)(t0 + t) * HID + h * HD + lc * 4];
        *(float4*)&Vs[t][lc * 4] =
            *(const float4*)&g_v[(size_t)(t0 + t) * HID + h * HD + lc * 4];
    }
    __syncthreads();

    const int tx = tid & 15, ty = tid >> 4;
    const int e0 = tx * 4, d0 = ty * 4;
    float acc[4][4];
#pragma unroll
    for (int i = 0; i < 4; i++)
#pragma unroll
        for (int j = 0; j < 4; j++) acc[i][j] = 0.f;

    for (int t = 0; t < CHUNK; t++) {
        float kf[4], vf[4];
#pragma unroll
        for (int i = 0; i < 4; i++) kf[i] = Ks[t][d0 + i];
#pragma unroll
        for (int j = 0; j < 4; j++) vf[j] = Vs[t][e0 + j];
#pragma unroll
        for (int i = 0; i < 4; i++)
#pragma unroll
            for (int j = 0; j < 4; j++) acc[i][j] = fmaf(kf[i], vf[j], acc[i][j]);
    }

    float* Sout = g_S + (size_t)(h * NCHUNK + c) * HD * HD;
#pragma unroll
    for (int i = 0; i < 4; i++)
#pragma unroll
        for (int j = 0; j < 4; j++) Sout[(d0 + i) * HD + e0 + j] = acc[i][j];

    if (tid < HD) {
        float z = 0.f;
        for (int t = 0; t < CHUNK; t++) z += Ks[t][tid];
        g_Z[(size_t)(h * NCHUNK + c) * HD + tid] = z;
    }
}

// ---------------- Pass B: exclusive scan over chunks ----------------
__global__ __launch_bounds__(256) void chunk_scan_kernel()
{
    const int h = blockIdx.x;
    const int tid = threadIdx.x;
    float acc[16];
#pragma unroll
    for (int i = 0; i < 16; i++) acc[i] = 0.f;

    float* Sh = g_S + (size_t)h * NCHUNK * HD * HD;
    for (int c = 0; c < NCHUNK; c++) {
        float* p = Sh + (size_t)c * HD * HD;
#pragma unroll
        for (int i = 0; i < 16; i++) {
            const int e = i * 256 + tid;
            const float v = p[e];
            p[e] = acc[i];
            acc[i] += v;
        }
    }
    if (tid < HD) {
        float az = 0.f;
        float* Zh = g_Z + (size_t)h * NCHUNK * HD;
        for (int c = 0; c < NCHUNK; c++) {
            const float v = Zh[c * HD + tid];
            Zh[c * HD + tid] = az;
            az += v;
        }
    }
}

// ---------------- Pass C: per-chunk output (conflict-free) ----------------
#define KTS 68   // Kt row stride (floats), 16B-aligned rows
extern __shared__ float sm_c[];
__global__ __launch_bounds__(256) void chunk_out_kernel()
{
    const int c = blockIdx.x;
    const int h = blockIdx.y;
    float* Qs = sm_c;                    // [64][64]
    float* Kt = sm_c + 4096;             // [64][KTS] transposed K; later reused as V [64][64]
    float* Sp = sm_c + 4096 + 64 * KTS;  // [64][64]
    float* Am = Sp + 4096;               // [64][64]
    __shared__ float zprev[HD];
    __shared__ float dinv[CHUNK];

    const int tid = threadIdx.x;
    const int t0 = c * CHUNK;
    const int lr = tid >> 4;
    const int lc = tid & 15;

#pragma unroll
    for (int p = 0; p < 4; p++) {
        const int t = lr + p * 16;
        float4 qv = *(const float4*)&g_q[(size_t)(t0 + t) * HID + h * HD + lc * 4];
        *(float4*)&Qs[t * HD + lc * 4] = qv;
        float4 kv = *(const float4*)&g_k[(size_t)(t0 + t) * HID + h * HD + lc * 4];
        // transposed store: Kt[d][t]
        Kt[(lc * 4 + 0) * KTS + t] = kv.x;
        Kt[(lc * 4 + 1) * KTS + t] = kv.y;
        Kt[(lc * 4 + 2) * KTS + t] = kv.z;
        Kt[(lc * 4 + 3) * KTS + t] = kv.w;
    }
    {
        const float* Sg = g_S + (size_t)(h * NCHUNK + c) * HD * HD;
#pragma unroll
        for (int i = 0; i < 4; i++)
            *(float4*)&Sp[i * 1024 + tid * 4] = *(const float4*)&Sg[i * 1024 + tid * 4];
    }
    if (tid < HD) zprev[tid] = g_Z[(size_t)(h * NCHUNK + c) * HD + tid];
    __syncthreads();

    const int tx = tid & 15, ty = tid >> 4;
    const int trow = ty * 4, scol = tx * 4;

    // A = tril(Q K^T): kf via conflict-free float4 from Kt
    float a[4][4];
#pragma unroll
    for (int i = 0; i < 4; i++)
#pragma unroll
        for (int j = 0; j < 4; j++) a[i][j] = 0.f;
    for (int d = 0; d < HD; d++) {
        const float4 kf = *(const float4*)&Kt[d * KTS + scol];
        float qf[4];
#pragma unroll
        for (int i = 0; i < 4; i++) qf[i] = Qs[(trow + i) * HD + d];
#pragma unroll
        for (int i = 0; i < 4; i++) {
            a[i][0] = fmaf(qf[i], kf.x, a[i][0]);
            a[i][1] = fmaf(qf[i], kf.y, a[i][1]);
            a[i][2] = fmaf(qf[i], kf.z, a[i][2]);
            a[i][3] = fmaf(qf[i], kf.w, a[i][3]);
        }
    }
    // mask + write Am + register-side row sums (rowsum + q.zprev partials)
    float tot[4];
#pragma unroll
    for (int i = 0; i < 4; i++) {
        float rs = 0.f;
#pragma unroll
        for (int j = 0; j < 4; j++) {
            if (scol + j > trow + i) a[i][j] = 0.f;
            rs += a[i][j];
        }
        float qz = 0.f;
#pragma unroll
        for (int j = 0; j < 4; j++)
            qz = fmaf(Qs[(trow + i) * HD + scol + j], zprev[scol + j], qz);
        tot[i] = rs + qz;
        *(float4*)&Am[(trow + i) * CHUNK + scol] = make_float4(a[i][0], a[i][1], a[i][2], a[i][3]);
    }
#pragma unroll
    for (int m = 1; m < 16; m <<= 1)
#pragma unroll
        for (int i = 0; i < 4; i++)
            tot[i] += __shfl_xor_sync(0xffffffffu, tot[i], m);
    if (tx == 0) {
#pragma unroll
        for (int i = 0; i < 4; i++)
            dinv[trow + i] = 1.f / fmaxf(tot[i], 1e-6f);
    }
    __syncthreads();   // Am + dinv ready; Kt reads done

    // reuse Kt region as V [64][64]
    float* Vs = Kt;
#pragma unroll
    for (int p = 0; p < 4; p++) {
        const int t = lr + p * 16;
        *(float4*)&Vs[t * HD + lc * 4] =
            *(const float4*)&g_v[(size_t)(t0 + t) * HID + h * HD + lc * 4];
    }
    __syncthreads();

    // O = Q @ Sp + Am @ V
    float o[4][4];
#pragma unroll
    for (int i = 0; i < 4; i++)
#pragma unroll
        for (int j = 0; j < 4; j++) o[i][j] = 0.f;
    for (int d = 0; d < HD; d++) {
        const float4 sf = *(const float4*)&Sp[d * HD + scol];
        float qf[4];
#pragma unroll
        for (int i = 0; i < 4; i++) qf[i] = Qs[(trow + i) * HD + d];
#pragma unroll
        for (int i = 0; i < 4; i++) {
            o[i][0] = fmaf(qf[i], sf.x, o[i][0]);
            o[i][1] = fmaf(qf[i], sf.y, o[i][1]);
            o[i][2] = fmaf(qf[i], sf.z, o[i][2]);
            o[i][3] = fmaf(qf[i], sf.w, o[i][3]);
        }
    }
    for (int s = 0; s < CHUNK; s++) {
        const float4 vf = *(const float4*)&Vs[s * HD + scol];
        float af[4];
#pragma unroll
        for (int i = 0; i < 4; i++) af[i] = Am[(trow + i) * CHUNK + s];
#pragma unroll
        for (int i = 0; i < 4; i++) {
            o[i][0] = fmaf(af[i], vf.x, o[i][0]);
            o[i][1] = fmaf(af[i], vf.y, o[i][1]);
            o[i][2] = fmaf(af[i], vf.z, o[i][2]);
            o[i][3] = fmaf(af[i], vf.w, o[i][3]);
        }
    }
#pragma unroll
    for (int i = 0; i < 4; i++) {
        const float di = dinv[trow + i];
        float4 r;
        r.x = rndtf32(o[i][0] * di);
        r.y = rndtf32(o[i][1] * di);
        r.z = rndtf32(o[i][2] * di);
        r.w = rndtf32(o[i][3] * di);
        *(float4*)&g_att[(size_t)(t0 + trow + i) * HID + h * HD + scol] = r;
    }
}

#define CO_SMEM ((4096 * 3 + 64 * KTS) * 4)

// ---------------- launch ----------------
extern "C" void kernel_launch(void* const* d_in, const int* in_sizes, int n_in,
                              void* d_out, int out_size)
{
    const float* x  = (const float*)d_in[0];
    const float* Wq = (const float*)d_in[1];
    const float* Wk = (const float*)d_in[2];
    const float* Wv = (const float*)d_in[3];
    const float* Wo = (const float*)d_in[4];
    float* out = (float*)d_out;

    float *xr, *wqr, *wkr, *wvr, *wor;
    cudaGetSymbolAddress((void**)&xr,  g_xr);
    cudaGetSymbolAddress((void**)&wqr, g_wqr);
    cudaGetSymbolAddress((void**)&wkr, g_wkr);
    cudaGetSymbolAddress((void**)&wvr, g_wvr);
    cudaGetSymbolAddress((void**)&wor, g_wor);

    static int attr_set = 0;
    if (!attr_set) {
        cudaFuncSetAttribute(chunk_out_kernel,
                             cudaFuncAttributeMaxDynamicSharedMemorySize, CO_SMEM);
        cudaFuncSetAttribute(gemm_qkv_kernel,
                             cudaFuncAttributeMaxDynamicSharedMemorySize, GEMM_SMEM);
        cudaFuncSetAttribute(gemm_out_kernel,
                             cudaFuncAttributeMaxDynamicSharedMemorySize, GEMM_SMEM);
        attr_set = 1;
    }

    const int NX4 = SEQ * HID / 4;
    const int NW4 = HID * HID / 4;
    round_kernel<<<(NX4 + 255) / 256, 256>>>(x, xr, NX4);
    round_kernel<<<(NW4 + 255) / 256, 256>>>(Wq, wqr, NW4);
    round_kernel<<<(NW4 + 255) / 256, 256>>>(Wk, wkr, NW4);
    round_kernel<<<(NW4 + 255) / 256, 256>>>(Wv, wvr, NW4);
    round_kernel<<<(NW4 + 255) / 256, 256>>>(Wo, wor, NW4);

    dim3 gq(HID / 128, SEQ / 128, 3);
    gemm_qkv_kernel<<<gq, 256, GEMM_SMEM>>>();

    chunk_stats_kernel<<<dim3(NCHUNK, NH), 256>>>();
    chunk_scan_kernel<<<NH, 256>>>();
    chunk_out_kernel<<<dim3(NCHUNK, NH), 256, CO_SMEM>>>();

    dim3 go(HID / 128, SEQ / 128);
    gemm_out_kernel<<<go, 256, GEMM_SMEM>>>(out);
}

// round 10
// speedup vs baseline: 3.0842x; 1.0803x over previous
#include <cuda_runtime.h>
#include <math.h>
#include <stdint.h>

#define SEQ 2048
#define HID 1024
#define NH 16
#define HD 64
#define CHUNK 64
#define NCHUNK (SEQ / CHUNK)

// ---------------- scratch ----------------
__device__ float g_q[SEQ * HID];
__device__ float g_k[SEQ * HID];
__device__ float g_v[SEQ * HID];
__device__ float g_att[SEQ * HID];            // pre-rounded to tf32
__device__ float g_S[NH * NCHUNK * HD * HD];  // stored TRANSPOSED: S_store[e][d] = S[d][e]
__device__ float g_Z[NH * NCHUNK * HD];
__device__ float g_xr[SEQ * HID];
__device__ float g_wqr[HID * HID];
__device__ float g_wkr[HID * HID];
__device__ float g_wvr[HID * HID];
__device__ float g_wor[HID * HID];

__device__ __forceinline__ uint32_t f2tf32(float f) {
    uint32_t u;
    asm("cvt.rna.tf32.f32 %0, %1;" : "=r"(u) : "f"(f));
    return u;
}
__device__ __forceinline__ float rndtf32(float f) { return __uint_as_float(f2tf32(f)); }
__device__ __forceinline__ uint32_t smem_u32(const void* p) {
    uint32_t a;
    asm("{ .reg .u64 t; cvta.to.shared.u64 t, %1; cvt.u32.u64 %0, t; }" : "=r"(a) : "l"(p));
    return a;
}
// split f into tf32 hi + lo for 3xTF32 compensated MMA
__device__ __forceinline__ void split32(float f, uint32_t& hi, uint32_t& lo) {
    float fh = rndtf32(f);
    hi = __float_as_uint(fh);
    lo = f2tf32(f - fh);
}

#define MMA_TF32(c0,c1,c2,c3,a0,a1,a2,a3,b0,b1) \
    asm volatile("mma.sync.aligned.m16n8k8.row.col.f32.tf32.tf32.f32 " \
                 "{%0,%1,%2,%3}, {%4,%5,%6,%7}, {%8,%9}, {%0,%1,%2,%3};" \
                 : "+f"(c0), "+f"(c1), "+f"(c2), "+f"(c3) \
                 : "r"(a0), "r"(a1), "r"(a2), "r"(a3), "r"(b0), "r"(b1))

// 3xTF32: C += ah*bh + ah*bl + al*bh  (~fp32 accuracy)
#define MMA3(C, ah, al, bh, bl) do { \
    MMA_TF32(C[0],C[1],C[2],C[3], ah[0],ah[1],ah[2],ah[3], bh[0],bh[1]); \
    MMA_TF32(C[0],C[1],C[2],C[3], ah[0],ah[1],ah[2],ah[3], bl[0],bl[1]); \
    MMA_TF32(C[0],C[1],C[2],C[3], al[0],al[1],al[2],al[3], bh[0],bh[1]); \
} while (0)

// ---------------- fused pre-round pass ----------------
#define X4 (SEQ * HID / 4)
#define W4 (HID * HID / 4)
__global__ __launch_bounds__(256) void round_all_kernel(
    const float* __restrict__ x, const float* __restrict__ Wq,
    const float* __restrict__ Wk, const float* __restrict__ Wv,
    const float* __restrict__ Wo)
{
    int i = blockIdx.x * 256 + threadIdx.x;
    const float4* src;
    float4* dst;
    int off;
    if (i < X4) { src = (const float4*)x; dst = (float4*)g_xr; off = i; }
    else {
        int j = i - X4;
        int seg = j >> 18;
        off = j & (W4 - 1);
        src = (const float4*)((seg == 0) ? Wq : (seg == 1) ? Wk : (seg == 2) ? Wv : Wo);
        dst = (float4*)((seg == 0) ? g_wqr : (seg == 1) ? g_wkr : (seg == 2) ? g_wvr : g_wor);
    }
    float4 v = src[off];
    v.x = rndtf32(v.x); v.y = rndtf32(v.y); v.z = rndtf32(v.z); v.w = rndtf32(v.w);
    dst[off] = v;
}

// ================= pipelined tf32 mma GEMM =================
#define GBK 32
#define GSTRIDE 36
#define NSTAGE (HID / GBK)
#define NBUF 3
#define TILE_FLOATS (128 * GSTRIDE)
#define STAGE_FLOATS (2 * TILE_FLOATS)
#define GEMM_SMEM (NBUF * STAGE_FLOATS * 4)

__device__ __forceinline__ void cpasync16(uint32_t saddr, const float* gaddr) {
    asm volatile("cp.async.cg.shared.global [%0], [%1], 16;" :: "r"(saddr), "l"(gaddr));
}

__device__ __forceinline__ void gemm_body(const float* __restrict__ A,
                                          const float* __restrict__ B,
                                          float* __restrict__ C, int act,
                                          int m0, int n0, char* smem)
{
    const uint32_t sbase = smem_u32(smem);
    const int tid = threadIdx.x;
    const int w = tid >> 5;
    const int lane = tid & 31;
    const int g = lane >> 2;
    const int l4 = lane & 3;
    const int wm = (w >> 2) * 64;
    const int wn = (w & 3) * 32;

    float c[4][4][4];
#pragma unroll
    for (int mi = 0; mi < 4; mi++)
#pragma unroll
        for (int ni = 0; ni < 4; ni++)
#pragma unroll
            for (int q = 0; q < 4; q++) c[mi][ni][q] = 0.f;

    auto prefetch = [&](int s) {
        const int b = s % NBUF;
        const uint32_t ab = sbase + (uint32_t)(b * STAGE_FLOATS) * 4;
        const uint32_t bb = ab + TILE_FLOATS * 4;
        const int k0 = s * GBK;
#pragma unroll
        for (int p = 0; p < 4; p++) {
            const int idx = tid + p * 256;
            const int r = idx >> 3, kk = (idx & 7) * 4;
            cpasync16(ab + (r * GSTRIDE + kk) * 4, &A[(size_t)(m0 + r) * HID + k0 + kk]);
            cpasync16(bb + (r * GSTRIDE + kk) * 4, &B[(size_t)(n0 + r) * HID + k0 + kk]);
        }
        asm volatile("cp.async.commit_group;" ::: "memory");
    };

    prefetch(0);
    prefetch(1);

    for (int s = 0; s < NSTAGE; s++) {
        asm volatile("cp.async.wait_group 1;" ::: "memory");
        __syncthreads();
        if (s + 2 < NSTAGE) prefetch(s + 2);

        const int b = s % NBUF;
        const float* As = (const float*)(smem) + b * STAGE_FLOATS;
        const float* Bs = As + TILE_FLOATS;

#pragma unroll
        for (int kk = 0; kk < GBK; kk += 8) {
            uint32_t a[4][4], bq[4][2];
#pragma unroll
            for (int mi = 0; mi < 4; mi++) {
                const int r = wm + mi * 16 + g;
                a[mi][0] = __float_as_uint(As[r * GSTRIDE + kk + l4]);
                a[mi][1] = __float_as_uint(As[(r + 8) * GSTRIDE + kk + l4]);
                a[mi][2] = __float_as_uint(As[r * GSTRIDE + kk + l4 + 4]);
                a[mi][3] = __float_as_uint(As[(r + 8) * GSTRIDE + kk + l4 + 4]);
            }
#pragma unroll
            for (int ni = 0; ni < 4; ni++) {
                const int r = wn + ni * 8 + g;
                bq[ni][0] = __float_as_uint(Bs[r * GSTRIDE + kk + l4]);
                bq[ni][1] = __float_as_uint(Bs[r * GSTRIDE + kk + l4 + 4]);
            }
#pragma unroll
            for (int mi = 0; mi < 4; mi++)
#pragma unroll
                for (int ni = 0; ni < 4; ni++)
                    MMA_TF32(c[mi][ni][0], c[mi][ni][1], c[mi][ni][2], c[mi][ni][3],
                             a[mi][0], a[mi][1], a[mi][2], a[mi][3],
                             bq[ni][0], bq[ni][1]);
        }
        __syncthreads();
    }
    asm volatile("cp.async.wait_group 0;" ::: "memory");

#pragma unroll
    for (int mi = 0; mi < 4; mi++) {
#pragma unroll
        for (int ri = 0; ri < 2; ri++) {
            const int m = m0 + wm + mi * 16 + g + ri * 8;
#pragma unroll
            for (int ni = 0; ni < 4; ni++) {
                float y0 = c[mi][ni][ri * 2 + 0];
                float y1 = c[mi][ni][ri * 2 + 1];
                if (act) {
                    y0 = (y0 > 0.f) ? (y0 + 1.f) : expf(y0);
                    y1 = (y1 > 0.f) ? (y1 + 1.f) : expf(y1);
                }
                const int n = n0 + wn + ni * 8 + l4 * 2;
                *(float2*)&C[(size_t)m * HID + n] = make_float2(y0, y1);
            }
        }
    }
}

extern __shared__ char sm_g[];
__global__ __launch_bounds__(256, 2) void gemm_qkv_kernel()
{
    const int z = blockIdx.z;
    const float* W = (z == 0) ? g_wqr : (z == 1) ? g_wkr : g_wvr;
    float* dst = (z == 0) ? g_q : (z == 1) ? g_k : g_v;
    gemm_body(g_xr, W, dst, z != 2, blockIdx.y * 128, blockIdx.x * 128, sm_g);
}
__global__ __launch_bounds__(256, 2) void gemm_out_kernel(float* __restrict__ out)
{
    gemm_body(g_att, g_wor, out, 0, blockIdx.y * 128, blockIdx.x * 128, sm_g);
}

// ================= Pass A: per-chunk S=K^T V (3xTF32), z=sum(k) =================
#define PS 68
__global__ __launch_bounds__(256) void chunk_stats_kernel()
{
    const int c = blockIdx.x;
    const int h = blockIdx.y;
    __shared__ float Kt[64 * PS];   // Kt[d][t]
    __shared__ float Vt[64 * PS];   // Vt[e][t]

    const int tid = threadIdx.x;
    const int t0 = c * CHUNK;

#pragma unroll
    for (int p = 0; p < 4; p++) {
        const int idx = tid + p * 256;
        const int t = idx >> 4;
        const int e4 = (idx & 15) * 4;
        float4 kv = *(const float4*)&g_k[(size_t)(t0 + t) * HID + h * HD + e4];
        Kt[(e4 + 0) * PS + t] = kv.x; Kt[(e4 + 1) * PS + t] = kv.y;
        Kt[(e4 + 2) * PS + t] = kv.z; Kt[(e4 + 3) * PS + t] = kv.w;
        float4 vv = *(const float4*)&g_v[(size_t)(t0 + t) * HID + h * HD + e4];
        Vt[(e4 + 0) * PS + t] = vv.x; Vt[(e4 + 1) * PS + t] = vv.y;
        Vt[(e4 + 2) * PS + t] = vv.z; Vt[(e4 + 3) * PS + t] = vv.w;
    }
    __syncthreads();

    if (tid < HD) {
        float z = 0.f;
        for (int t = 0; t < CHUNK; t++) z += Kt[tid * PS + t];
        g_Z[(size_t)(h * NCHUNK + c) * HD + tid] = z;
    }

    const int w = tid >> 5, lane = tid & 31;
    const int g = lane >> 2, l4 = lane & 3;
    const int wm = (w >> 1) * 16;
    const int wn = (w & 1) * 32;

    float cc[4][4];
#pragma unroll
    for (int ni = 0; ni < 4; ni++)
#pragma unroll
        for (int q = 0; q < 4; q++) cc[ni][q] = 0.f;

#pragma unroll
    for (int ks = 0; ks < 8; ks++) {
        const int k0 = ks * 8;
        uint32_t ah[4], al[4];
        split32(Vt[(wm + g) * PS + k0 + l4],         ah[0], al[0]);
        split32(Vt[(wm + g + 8) * PS + k0 + l4],     ah[1], al[1]);
        split32(Vt[(wm + g) * PS + k0 + l4 + 4],     ah[2], al[2]);
        split32(Vt[(wm + g + 8) * PS + k0 + l4 + 4], ah[3], al[3]);
#pragma unroll
        for (int ni = 0; ni < 4; ni++) {
            const int d = wn + ni * 8 + g;
            uint32_t bh[2], bl[2];
            split32(Kt[d * PS + k0 + l4],     bh[0], bl[0]);
            split32(Kt[d * PS + k0 + l4 + 4], bh[1], bl[1]);
            MMA3(cc[ni], ah, al, bh, bl);
        }
    }

    float* Sout = g_S + (size_t)(h * NCHUNK + c) * HD * HD;
#pragma unroll
    for (int ni = 0; ni < 4; ni++) {
        const int d = wn + ni * 8 + l4 * 2;
        *(float2*)&Sout[(wm + g) * HD + d]     = make_float2(cc[ni][0], cc[ni][1]);
        *(float2*)&Sout[(wm + g + 8) * HD + d] = make_float2(cc[ni][2], cc[ni][3]);
    }
}

// ---------------- Pass B: exclusive scan over chunks ----------------
__global__ __launch_bounds__(256) void chunk_scan_kernel()
{
    const int h = blockIdx.x;
    const int tid = threadIdx.x;
    float acc[16];
#pragma unroll
    for (int i = 0; i < 16; i++) acc[i] = 0.f;

    float* Sh = g_S + (size_t)h * NCHUNK * HD * HD;
    for (int c = 0; c < NCHUNK; c++) {
        float* p = Sh + (size_t)c * HD * HD;
#pragma unroll
        for (int i = 0; i < 16; i++) {
            const int e = i * 256 + tid;
            const float v = p[e];
            p[e] = acc[i];
            acc[i] += v;
        }
    }
    if (tid < HD) {
        float az = 0.f;
        float* Zh = g_Z + (size_t)h * NCHUNK * HD;
        for (int c = 0; c < NCHUNK; c++) {
            const float v = Zh[c * HD + tid];
            Zh[c * HD + tid] = az;
            az += v;
        }
    }
}

// ================= Pass C: per-chunk output (3xTF32) =================
extern __shared__ float sm_c[];
__global__ __launch_bounds__(256) void chunk_out_kernel()
{
    const int c = blockIdx.x;
    const int h = blockIdx.y;
    float* Qs  = sm_c;                 // [64][PS] (t,d)
    float* Kb  = Qs + 64 * PS;         // [64][PS] (s,d)
    float* Spt = Kb + 64 * PS;         // [64][PS] S_store[e][d]
    float* Vt  = Spt + 64 * PS;        // [64][PS] Vt[e][s]
    float* Am  = Vt + 64 * PS;         // [64][PS] masked QK^T (t,s)
    __shared__ float zprev[HD];
    __shared__ float rowpart[HD][2];
    __shared__ float dinv[CHUNK];

    const int tid = threadIdx.x;
    const int t0 = c * CHUNK;

#pragma unroll
    for (int p = 0; p < 4; p++) {
        const int idx = tid + p * 256;
        const int r = idx >> 4;
        const int c4 = (idx & 15) * 4;
        *(float4*)&Qs[r * PS + c4] =
            *(const float4*)&g_q[(size_t)(t0 + r) * HID + h * HD + c4];
        *(float4*)&Kb[r * PS + c4] =
            *(const float4*)&g_k[(size_t)(t0 + r) * HID + h * HD + c4];
        *(float4*)&Spt[r * PS + c4] =
            *(const float4*)&g_S[(size_t)(h * NCHUNK + c) * HD * HD + r * HD + c4];
        float4 vv = *(const float4*)&g_v[(size_t)(t0 + r) * HID + h * HD + c4];
        Vt[(c4 + 0) * PS + r] = vv.x; Vt[(c4 + 1) * PS + r] = vv.y;
        Vt[(c4 + 2) * PS + r] = vv.z; Vt[(c4 + 3) * PS + r] = vv.w;
    }
    if (tid < HD) zprev[tid] = g_Z[(size_t)(h * NCHUNK + c) * HD + tid];
    __syncthreads();

    const int w = tid >> 5, lane = tid & 31;
    const int g = lane >> 2, l4 = lane & 3;
    const int wm = (w >> 1) * 16;
    const int wn = (w & 1) * 32;
    const int t1 = wm + g, t2 = wm + g + 8;

    // ---- product 1: QK^T (3xTF32) ----
    float c1[4][4];
#pragma unroll
    for (int ni = 0; ni < 4; ni++)
#pragma unroll
        for (int q = 0; q < 4; q++) c1[ni][q] = 0.f;
#pragma unroll
    for (int ks = 0; ks < 8; ks++) {
        const int k0 = ks * 8;
        uint32_t ah[4], al[4];
        split32(Qs[t1 * PS + k0 + l4],     ah[0], al[0]);
        split32(Qs[t2 * PS + k0 + l4],     ah[1], al[1]);
        split32(Qs[t1 * PS + k0 + l4 + 4], ah[2], al[2]);
        split32(Qs[t2 * PS + k0 + l4 + 4], ah[3], al[3]);
#pragma unroll
        for (int ni = 0; ni < 4; ni++) {
            const int s = wn + ni * 8 + g;
            uint32_t bh[2], bl[2];
            split32(Kb[s * PS + k0 + l4],     bh[0], bl[0]);
            split32(Kb[s * PS + k0 + l4 + 4], bh[1], bl[1]);
            MMA3(c1[ni], ah, al, bh, bl);
        }
    }
    // mask + write Am + row sums
    float tot1 = 0.f, tot2 = 0.f;
#pragma unroll
    for (int ni = 0; ni < 4; ni++) {
        const int s0 = wn + ni * 8 + 2 * l4;
        float m00 = (s0     <= t1) ? c1[ni][0] : 0.f;
        float m01 = (s0 + 1 <= t1) ? c1[ni][1] : 0.f;
        float m10 = (s0     <= t2) ? c1[ni][2] : 0.f;
        float m11 = (s0 + 1 <= t2) ? c1[ni][3] : 0.f;
        tot1 += m00 + m01;
        tot2 += m10 + m11;
        *(float2*)&Am[t1 * PS + s0] = make_float2(m00, m01);
        *(float2*)&Am[t2 * PS + s0] = make_float2(m10, m11);
    }
#pragma unroll
    for (int j = 0; j < 8; j++) {
        const int d = wn + l4 * 8 + j;
        tot1 = fmaf(Qs[t1 * PS + d], zprev[d], tot1);
        tot2 = fmaf(Qs[t2 * PS + d], zprev[d], tot2);
    }
#pragma unroll
    for (int m = 1; m < 4; m <<= 1) {
        tot1 += __shfl_xor_sync(0xffffffffu, tot1, m);
        tot2 += __shfl_xor_sync(0xffffffffu, tot2, m);
    }
    if (l4 == 0) {
        rowpart[t1][w & 1] = tot1;
        rowpart[t2][w & 1] = tot2;
    }
    __syncthreads();
    if (tid < CHUNK) dinv[tid] = 1.f / fmaxf(rowpart[tid][0] + rowpart[tid][1], 1e-6f);

    // ---- products 2+3: O = Q@Spt^T + Am@V (3xTF32) ----
    float o[4][4];
#pragma unroll
    for (int ni = 0; ni < 4; ni++)
#pragma unroll
        for (int q = 0; q < 4; q++) o[ni][q] = 0.f;
#pragma unroll
    for (int ks = 0; ks < 8; ks++) {
        const int k0 = ks * 8;
        uint32_t ah[4], al[4];
        split32(Qs[t1 * PS + k0 + l4],     ah[0], al[0]);
        split32(Qs[t2 * PS + k0 + l4],     ah[1], al[1]);
        split32(Qs[t1 * PS + k0 + l4 + 4], ah[2], al[2]);
        split32(Qs[t2 * PS + k0 + l4 + 4], ah[3], al[3]);
#pragma unroll
        for (int ni = 0; ni < 4; ni++) {
            const int e = wn + ni * 8 + g;
            uint32_t bh[2], bl[2];
            split32(Spt[e * PS + k0 + l4],     bh[0], bl[0]);
            split32(Spt[e * PS + k0 + l4 + 4], bh[1], bl[1]);
            MMA3(o[ni], ah, al, bh, bl);
        }
    }
#pragma unroll
    for (int ks = 0; ks < 8; ks++) {
        const int k0 = ks * 8;
        uint32_t ah[4], al[4];
        split32(Am[t1 * PS + k0 + l4],     ah[0], al[0]);
        split32(Am[t2 * PS + k0 + l4],     ah[1], al[1]);
        split32(Am[t1 * PS + k0 + l4 + 4], ah[2], al[2]);
        split32(Am[t2 * PS + k0 + l4 + 4], ah[3], al[3]);
#pragma unroll
        for (int ni = 0; ni < 4; ni++) {
            const int e = wn + ni * 8 + g;
            uint32_t bh[2], bl[2];
            split32(Vt[e * PS + k0 + l4],     bh[0], bl[0]);
            split32(Vt[e * PS + k0 + l4 + 4], bh[1], bl[1]);
            MMA3(o[ni], ah, al, bh, bl);
        }
    }
    __syncthreads();

    const float d1 = dinv[t1];
    const float d2 = dinv[t2];
#pragma unroll
    for (int ni = 0; ni < 4; ni++) {
        const int e0 = wn + ni * 8 + 2 * l4;
        float2 r1 = make_float2(rndtf32(o[ni][0] * d1), rndtf32(o[ni][1] * d1));
        float2 r2 = make_float2(rndtf32(o[ni][2] * d2), rndtf32(o[ni][3] * d2));
        *(float2*)&g_att[(size_t)(t0 + t1) * HID + h * HD + e0] = r1;
        *(float2*)&g_att[(size_t)(t0 + t2) * HID + h * HD + e0] = r2;
    }
}

#define CO_SMEM (5 * 64 * PS * 4)

// ---------------- launch ----------------
extern "C" void kernel_launch(void* const* d_in, const int* in_sizes, int n_in,
                              void* d_out, int out_size)
{
    const float* x  = (const float*)d_in[0];
    const float* Wq = (const float*)d_in[1];
    const float* Wk = (const float*)d_in[2];
    const float* Wv = (const float*)d_in[3];
    const float* Wo = (const float*)d_in[4];
    float* out = (float*)d_out;

    static int attr_set = 0;
    if (!attr_set) {
        cudaFuncSetAttribute(chunk_out_kernel,
                             cudaFuncAttributeMaxDynamicSharedMemorySize, CO_SMEM);
        cudaFuncSetAttribute(gemm_qkv_kernel,
                             cudaFuncAttributeMaxDynamicSharedMemorySize, GEMM_SMEM);
        cudaFuncSetAttribute(gemm_out_kernel,
                             cudaFuncAttributeMaxDynamicSharedMemorySize, GEMM_SMEM);
        attr_set = 1;
    }

    const int TOT4 = X4 + 4 * W4;
    round_all_kernel<<<TOT4 / 256, 256>>>(x, Wq, Wk, Wv, Wo);

    dim3 gq(HID / 128, SEQ / 128, 3);
    gemm_qkv_kernel<<<gq, 256, GEMM_SMEM>>>();

    chunk_stats_kernel<<<dim3(NCHUNK, NH), 256>>>();
    chunk_scan_kernel<<<NH, 256>>>();
    chunk_out_kernel<<<dim3(NCHUNK, NH), 256, CO_SMEM>>>();

    dim3 go(HID / 128, SEQ / 128);
    gemm_out_kernel<<<go, 256, GEMM_SMEM>>>(out);
}

// round 11
// speedup vs baseline: 3.4966x; 1.1337x over previous
#include <cuda_runtime.h>
#include <math.h>
#include <stdint.h>

#define SEQ 2048
#define HID 1024
#define NH 16
#define HD 64
#define CHUNK 64
#define NCHUNK (SEQ / CHUNK)

// ---------------- scratch ----------------
__device__ float g_q[SEQ * HID];
__device__ float g_k[SEQ * HID];
__device__ float g_v[SEQ * HID];
__device__ float g_att[SEQ * HID];            // pre-rounded to tf32
__device__ float g_S[NH * NCHUNK * HD * HD];  // stored TRANSPOSED: S_store[e][d] = S[d][e]
__device__ float g_Z[NH * NCHUNK * HD];
__device__ float g_xr[SEQ * HID];
__device__ float g_wqr[HID * HID];
__device__ float g_wkr[HID * HID];
__device__ float g_wvr[HID * HID];
__device__ float g_wor[HID * HID];

__device__ __forceinline__ uint32_t f2tf32(float f) {
    uint32_t u;
    asm("cvt.rna.tf32.f32 %0, %1;" : "=r"(u) : "f"(f));
    return u;
}
__device__ __forceinline__ float rndtf32(float f) { return __uint_as_float(f2tf32(f)); }
__device__ __forceinline__ uint32_t smem_u32(const void* p) {
    uint32_t a;
    asm("{ .reg .u64 t; cvta.to.shared.u64 t, %1; cvt.u32.u64 %0, t; }" : "=r"(a) : "l"(p));
    return a;
}
__device__ __forceinline__ void split32(float f, uint32_t& hi, uint32_t& lo) {
    float fh = rndtf32(f);
    hi = __float_as_uint(fh);
    lo = f2tf32(f - fh);
}

#define MMA_TF32(c0,c1,c2,c3,a0,a1,a2,a3,b0,b1) \
    asm volatile("mma.sync.aligned.m16n8k8.row.col.f32.tf32.tf32.f32 " \
                 "{%0,%1,%2,%3}, {%4,%5,%6,%7}, {%8,%9}, {%0,%1,%2,%3};" \
                 : "+f"(c0), "+f"(c1), "+f"(c2), "+f"(c3) \
                 : "r"(a0), "r"(a1), "r"(a2), "r"(a3), "r"(b0), "r"(b1))

#define MMA3(C, ah, al, bh, bl) do { \
    MMA_TF32(C[0],C[1],C[2],C[3], ah[0],ah[1],ah[2],ah[3], bh[0],bh[1]); \
    MMA_TF32(C[0],C[1],C[2],C[3], ah[0],ah[1],ah[2],ah[3], bl[0],bl[1]); \
    MMA_TF32(C[0],C[1],C[2],C[3], al[0],al[1],al[2],al[3], bh[0],bh[1]); \
} while (0)

// ---------------- fused pre-round pass ----------------
#define X4 (SEQ * HID / 4)
#define W4 (HID * HID / 4)
__global__ __launch_bounds__(256) void round_all_kernel(
    const float* __restrict__ x, const float* __restrict__ Wq,
    const float* __restrict__ Wk, const float* __restrict__ Wv,
    const float* __restrict__ Wo)
{
    int i = blockIdx.x * 256 + threadIdx.x;
    const float4* src;
    float4* dst;
    int off;
    if (i < X4) { src = (const float4*)x; dst = (float4*)g_xr; off = i; }
    else {
        int j = i - X4;
        int seg = j >> 18;
        off = j & (W4 - 1);
        src = (const float4*)((seg == 0) ? Wq : (seg == 1) ? Wk : (seg == 2) ? Wv : Wo);
        dst = (float4*)((seg == 0) ? g_wqr : (seg == 1) ? g_wkr : (seg == 2) ? g_wvr : g_wor);
    }
    float4 v = src[off];
    v.x = rndtf32(v.x); v.y = rndtf32(v.y); v.z = rndtf32(v.z); v.w = rndtf32(v.w);
    dst[off] = v;
}

// ================= pipelined tf32 mma GEMM =================
#define GBK 32
#define GSTRIDE 36
#define NSTAGE (HID / GBK)
#define NBUF 3
#define TILE_FLOATS (128 * GSTRIDE)
#define STAGE_FLOATS (2 * TILE_FLOATS)
#define GEMM_SMEM (NBUF * STAGE_FLOATS * 4)

__device__ __forceinline__ void cpasync16(uint32_t saddr, const float* gaddr) {
    asm volatile("cp.async.cg.shared.global [%0], [%1], 16;" :: "r"(saddr), "l"(gaddr));
}

__device__ __forceinline__ void gemm_body(const float* __restrict__ A,
                                          const float* __restrict__ B,
                                          float* __restrict__ C, int act,
                                          int m0, int n0, char* smem)
{
    const uint32_t sbase = smem_u32(smem);
    const int tid = threadIdx.x;
    const int w = tid >> 5;
    const int lane = tid & 31;
    const int g = lane >> 2;
    const int l4 = lane & 3;
    const int wm = (w >> 2) * 64;
    const int wn = (w & 3) * 32;

    float c[4][4][4];
#pragma unroll
    for (int mi = 0; mi < 4; mi++)
#pragma unroll
        for (int ni = 0; ni < 4; ni++)
#pragma unroll
            for (int q = 0; q < 4; q++) c[mi][ni][q] = 0.f;

    auto prefetch = [&](int s) {
        const int b = s % NBUF;
        const uint32_t ab = sbase + (uint32_t)(b * STAGE_FLOATS) * 4;
        const uint32_t bb = ab + TILE_FLOATS * 4;
        const int k0 = s * GBK;
#pragma unroll
        for (int p = 0; p < 4; p++) {
            const int idx = tid + p * 256;
            const int r = idx >> 3, kk = (idx & 7) * 4;
            cpasync16(ab + (r * GSTRIDE + kk) * 4, &A[(size_t)(m0 + r) * HID + k0 + kk]);
            cpasync16(bb + (r * GSTRIDE + kk) * 4, &B[(size_t)(n0 + r) * HID + k0 + kk]);
        }
        asm volatile("cp.async.commit_group;" ::: "memory");
    };

    prefetch(0);
    prefetch(1);

    for (int s = 0; s < NSTAGE; s++) {
        asm volatile("cp.async.wait_group 1;" ::: "memory");
        __syncthreads();
        if (s + 2 < NSTAGE) prefetch(s + 2);

        const int b = s % NBUF;
        const float* As = (const float*)(smem) + b * STAGE_FLOATS;
        const float* Bs = As + TILE_FLOATS;

#pragma unroll
        for (int kk = 0; kk < GBK; kk += 8) {
            uint32_t a[4][4], bq[4][2];
#pragma unroll
            for (int mi = 0; mi < 4; mi++) {
                const int r = wm + mi * 16 + g;
                a[mi][0] = __float_as_uint(As[r * GSTRIDE + kk + l4]);
                a[mi][1] = __float_as_uint(As[(r + 8) * GSTRIDE + kk + l4]);
                a[mi][2] = __float_as_uint(As[r * GSTRIDE + kk + l4 + 4]);
                a[mi][3] = __float_as_uint(As[(r + 8) * GSTRIDE + kk + l4 + 4]);
            }
#pragma unroll
            for (int ni = 0; ni < 4; ni++) {
                const int r = wn + ni * 8 + g;
                bq[ni][0] = __float_as_uint(Bs[r * GSTRIDE + kk + l4]);
                bq[ni][1] = __float_as_uint(Bs[r * GSTRIDE + kk + l4 + 4]);
            }
#pragma unroll
            for (int mi = 0; mi < 4; mi++)
#pragma unroll
                for (int ni = 0; ni < 4; ni++)
                    MMA_TF32(c[mi][ni][0], c[mi][ni][1], c[mi][ni][2], c[mi][ni][3],
                             a[mi][0], a[mi][1], a[mi][2], a[mi][3],
                             bq[ni][0], bq[ni][1]);
        }
        __syncthreads();
    }
    asm volatile("cp.async.wait_group 0;" ::: "memory");

#pragma unroll
    for (int mi = 0; mi < 4; mi++) {
#pragma unroll
        for (int ri = 0; ri < 2; ri++) {
            const int m = m0 + wm + mi * 16 + g + ri * 8;
#pragma unroll
            for (int ni = 0; ni < 4; ni++) {
                float y0 = c[mi][ni][ri * 2 + 0];
                float y1 = c[mi][ni][ri * 2 + 1];
                if (act) {
                    y0 = (y0 > 0.f) ? (y0 + 1.f) : expf(y0);
                    y1 = (y1 > 0.f) ? (y1 + 1.f) : expf(y1);
                }
                const int n = n0 + wn + ni * 8 + l4 * 2;
                *(float2*)&C[(size_t)m * HID + n] = make_float2(y0, y1);
            }
        }
    }
}

extern __shared__ char sm_g[];
__global__ __launch_bounds__(256, 2) void gemm_qkv_kernel()
{
    const int z = blockIdx.z;
    const float* W = (z == 0) ? g_wqr : (z == 1) ? g_wkr : g_wvr;
    float* dst = (z == 0) ? g_q : (z == 1) ? g_k : g_v;
    gemm_body(g_xr, W, dst, z != 2, blockIdx.y * 128, blockIdx.x * 128, sm_g);
}
__global__ __launch_bounds__(256, 2) void gemm_out_kernel(float* __restrict__ out)
{
    gemm_body(g_att, g_wor, out, 0, blockIdx.y * 128, blockIdx.x * 128, sm_g);
}

// ================= Pass A: per-chunk S=K^T V (3xTF32), z=sum(k) =================
#define PS 68
__global__ __launch_bounds__(256) void chunk_stats_kernel()
{
    const int c = blockIdx.x;
    const int h = blockIdx.y;
    __shared__ float Kt[64 * PS];   // Kt[d][t]
    __shared__ float Vt[64 * PS];   // Vt[e][t]

    const int tid = threadIdx.x;
    const int t0 = c * CHUNK;

#pragma unroll
    for (int p = 0; p < 4; p++) {
        const int idx = tid + p * 256;
        const int t = idx >> 4;
        const int e4 = (idx & 15) * 4;
        float4 kv = *(const float4*)&g_k[(size_t)(t0 + t) * HID + h * HD + e4];
        Kt[(e4 + 0) * PS + t] = kv.x; Kt[(e4 + 1) * PS + t] = kv.y;
        Kt[(e4 + 2) * PS + t] = kv.z; Kt[(e4 + 3) * PS + t] = kv.w;
        float4 vv = *(const float4*)&g_v[(size_t)(t0 + t) * HID + h * HD + e4];
        Vt[(e4 + 0) * PS + t] = vv.x; Vt[(e4 + 1) * PS + t] = vv.y;
        Vt[(e4 + 2) * PS + t] = vv.z; Vt[(e4 + 3) * PS + t] = vv.w;
    }
    __syncthreads();

    if (tid < HD) {
        float z = 0.f;
        for (int t = 0; t < CHUNK; t++) z += Kt[tid * PS + t];
        g_Z[(size_t)(h * NCHUNK + c) * HD + tid] = z;
    }

    const int w = tid >> 5, lane = tid & 31;
    const int g = lane >> 2, l4 = lane & 3;
    const int wm = (w >> 1) * 16;
    const int wn = (w & 1) * 32;

    float cc[4][4];
#pragma unroll
    for (int ni = 0; ni < 4; ni++)
#pragma unroll
        for (int q = 0; q < 4; q++) cc[ni][q] = 0.f;

#pragma unroll
    for (int ks = 0; ks < 8; ks++) {
        const int k0 = ks * 8;
        uint32_t ah[4], al[4];
        split32(Vt[(wm + g) * PS + k0 + l4],         ah[0], al[0]);
        split32(Vt[(wm + g + 8) * PS + k0 + l4],     ah[1], al[1]);
        split32(Vt[(wm + g) * PS + k0 + l4 + 4],     ah[2], al[2]);
        split32(Vt[(wm + g + 8) * PS + k0 + l4 + 4], ah[3], al[3]);
#pragma unroll
        for (int ni = 0; ni < 4; ni++) {
            const int d = wn + ni * 8 + g;
            uint32_t bh[2], bl[2];
            split32(Kt[d * PS + k0 + l4],     bh[0], bl[0]);
            split32(Kt[d * PS + k0 + l4 + 4], bh[1], bl[1]);
            MMA3(cc[ni], ah, al, bh, bl);
        }
    }

    float* Sout = g_S + (size_t)(h * NCHUNK + c) * HD * HD;
#pragma unroll
    for (int ni = 0; ni < 4; ni++) {
        const int d = wn + ni * 8 + l4 * 2;
        *(float2*)&Sout[(wm + g) * HD + d]     = make_float2(cc[ni][0], cc[ni][1]);
        *(float2*)&Sout[(wm + g + 8) * HD + d] = make_float2(cc[ni][2], cc[ni][3]);
    }
}

// ---------------- Pass B: PARALLEL exclusive scan over chunks ----------------
// One thread per (head, element) lane: 16*4096 = 65536 threads for S,
// plus 16*64 = 1024 threads (blocks 256..259) for Z.
#define SCAN_S_BLOCKS (NH * HD * HD / 256)   // 256
__global__ __launch_bounds__(256) void chunk_scan_kernel()
{
    const int bid = blockIdx.x;
    const int tid = threadIdx.x;
    if (bid < SCAN_S_BLOCKS) {
        const int gidx = bid * 256 + tid;         // 0 .. 65535
        const int h = gidx >> 12;                 // / 4096
        const int e = gidx & 4095;
        float* p = g_S + (size_t)h * NCHUNK * HD * HD + e;
        float acc = 0.f;
#pragma unroll 4
        for (int c = 0; c < NCHUNK; c++) {
            const float v = p[(size_t)c * HD * HD];
            p[(size_t)c * HD * HD] = acc;
            acc += v;
        }
    } else {
        const int j = (bid - SCAN_S_BLOCKS) * 256 + tid;   // 0 .. 1023
        const int h = j >> 6;
        const int d = j & 63;
        float* p = g_Z + (size_t)h * NCHUNK * HD + d;
        float acc = 0.f;
#pragma unroll 4
        for (int c = 0; c < NCHUNK; c++) {
            const float v = p[c * HD];
            p[c * HD] = acc;
            acc += v;
        }
    }
}

// ================= Pass C: per-chunk output (3xTF32) =================
extern __shared__ float sm_c[];
__global__ __launch_bounds__(256) void chunk_out_kernel()
{
    const int c = blockIdx.x;
    const int h = blockIdx.y;
    float* Qs  = sm_c;                 // [64][PS] (t,d)
    float* Kb  = Qs + 64 * PS;         // [64][PS] (s,d)
    float* Spt = Kb + 64 * PS;         // [64][PS] S_store[e][d]
    float* Vt  = Spt + 64 * PS;        // [64][PS] Vt[e][s]
    float* Am  = Vt + 64 * PS;         // [64][PS] masked QK^T (t,s)
    __shared__ float zprev[HD];
    __shared__ float rowpart[HD][2];
    __shared__ float dinv[CHUNK];

    const int tid = threadIdx.x;
    const int t0 = c * CHUNK;

#pragma unroll
    for (int p = 0; p < 4; p++) {
        const int idx = tid + p * 256;
        const int r = idx >> 4;
        const int c4 = (idx & 15) * 4;
        *(float4*)&Qs[r * PS + c4] =
            *(const float4*)&g_q[(size_t)(t0 + r) * HID + h * HD + c4];
        *(float4*)&Kb[r * PS + c4] =
            *(const float4*)&g_k[(size_t)(t0 + r) * HID + h * HD + c4];
        *(float4*)&Spt[r * PS + c4] =
            *(const float4*)&g_S[(size_t)(h * NCHUNK + c) * HD * HD + r * HD + c4];
        float4 vv = *(const float4*)&g_v[(size_t)(t0 + r) * HID + h * HD + c4];
        Vt[(c4 + 0) * PS + r] = vv.x; Vt[(c4 + 1) * PS + r] = vv.y;
        Vt[(c4 + 2) * PS + r] = vv.z; Vt[(c4 + 3) * PS + r] = vv.w;
    }
    if (tid < HD) zprev[tid] = g_Z[(size_t)(h * NCHUNK + c) * HD + tid];
    __syncthreads();

    const int w = tid >> 5, lane = tid & 31;
    const int g = lane >> 2, l4 = lane & 3;
    const int wm = (w >> 1) * 16;
    const int wn = (w & 1) * 32;
    const int t1 = wm + g, t2 = wm + g + 8;

    // ---- product 1: QK^T (3xTF32) ----
    float c1[4][4];
#pragma unroll
    for (int ni = 0; ni < 4; ni++)
#pragma unroll
        for (int q = 0; q < 4; q++) c1[ni][q] = 0.f;
#pragma unroll
    for (int ks = 0; ks < 8; ks++) {
        const int k0 = ks * 8;
        uint32_t ah[4], al[4];
        split32(Qs[t1 * PS + k0 + l4],     ah[0], al[0]);
        split32(Qs[t2 * PS + k0 + l4],     ah[1], al[1]);
        split32(Qs[t1 * PS + k0 + l4 + 4], ah[2], al[2]);
        split32(Qs[t2 * PS + k0 + l4 + 4], ah[3], al[3]);
#pragma unroll
        for (int ni = 0; ni < 4; ni++) {
            const int s = wn + ni * 8 + g;
            uint32_t bh[2], bl[2];
            split32(Kb[s * PS + k0 + l4],     bh[0], bl[0]);
            split32(Kb[s * PS + k0 + l4 + 4], bh[1], bl[1]);
            MMA3(c1[ni], ah, al, bh, bl);
        }
    }
    // mask + write Am + row sums
    float tot1 = 0.f, tot2 = 0.f;
#pragma unroll
    for (int ni = 0; ni < 4; ni++) {
        const int s0 = wn + ni * 8 + 2 * l4;
        float m00 = (s0     <= t1) ? c1[ni][0] : 0.f;
        float m01 = (s0 + 1 <= t1) ? c1[ni][1] : 0.f;
        float m10 = (s0     <= t2) ? c1[ni][2] : 0.f;
        float m11 = (s0 + 1 <= t2) ? c1[ni][3] : 0.f;
        tot1 += m00 + m01;
        tot2 += m10 + m11;
        *(float2*)&Am[t1 * PS + s0] = make_float2(m00, m01);
        *(float2*)&Am[t2 * PS + s0] = make_float2(m10, m11);
    }
#pragma unroll
    for (int j = 0; j < 8; j++) {
        const int d = wn + l4 * 8 + j;
        tot1 = fmaf(Qs[t1 * PS + d], zprev[d], tot1);
        tot2 = fmaf(Qs[t2 * PS + d], zprev[d], tot2);
    }
#pragma unroll
    for (int m = 1; m < 4; m <<= 1) {
        tot1 += __shfl_xor_sync(0xffffffffu, tot1, m);
        tot2 += __shfl_xor_sync(0xffffffffu, tot2, m);
    }
    if (l4 == 0) {
        rowpart[t1][w & 1] = tot1;
        rowpart[t2][w & 1] = tot2;
    }
    __syncthreads();
    if (tid < CHUNK) dinv[tid] = 1.f / fmaxf(rowpart[tid][0] + rowpart[tid][1], 1e-6f);

    // ---- products 2+3: O = Q@Spt^T + Am@V (3xTF32) ----
    float o[4][4];
#pragma unroll
    for (int ni = 0; ni < 4; ni++)
#pragma unroll
        for (int q = 0; q < 4; q++) o[ni][q] = 0.f;
#pragma unroll
    for (int ks = 0; ks < 8; ks++) {
        const int k0 = ks * 8;
        uint32_t ah[4], al[4];
        split32(Qs[t1 * PS + k0 + l4],     ah[0], al[0]);
        split32(Qs[t2 * PS + k0 + l4],     ah[1], al[1]);
        split32(Qs[t1 * PS + k0 + l4 + 4], ah[2], al[2]);
        split32(Qs[t2 * PS + k0 + l4 + 4], ah[3], al[3]);
#pragma unroll
        for (int ni = 0; ni < 4; ni++) {
            const int e = wn + ni * 8 + g;
            uint32_t bh[2], bl[2];
            split32(Spt[e * PS + k0 + l4],     bh[0], bl[0]);
            split32(Spt[e * PS + k0 + l4 + 4], bh[1], bl[1]);
            MMA3(o[ni], ah, al, bh, bl);
        }
    }
#pragma unroll
    for (int ks = 0; ks < 8; ks++) {
        const int k0 = ks * 8;
        uint32_t ah[4], al[4];
        split32(Am[t1 * PS + k0 + l4],     ah[0], al[0]);
        split32(Am[t2 * PS + k0 + l4],     ah[1], al[1]);
        split32(Am[t1 * PS + k0 + l4 + 4], ah[2], al[2]);
        split32(Am[t2 * PS + k0 + l4 + 4], ah[3], al[3]);
#pragma unroll
        for (int ni = 0; ni < 4; ni++) {
            const int e = wn + ni * 8 + g;
            uint32_t bh[2], bl[2];
            split32(Vt[e * PS + k0 + l4],     bh[0], bl[0]);
            split32(Vt[e * PS + k0 + l4 + 4], bh[1], bl[1]);
            MMA3(o[ni], ah, al, bh, bl);
        }
    }
    __syncthreads();

    const float d1 = dinv[t1];
    const float d2 = dinv[t2];
#pragma unroll
    for (int ni = 0; ni < 4; ni++) {
        const int e0 = wn + ni * 8 + 2 * l4;
        float2 r1 = make_float2(rndtf32(o[ni][0] * d1), rndtf32(o[ni][1] * d1));
        float2 r2 = make_float2(rndtf32(o[ni][2] * d2), rndtf32(o[ni][3] * d2));
        *(float2*)&g_att[(size_t)(t0 + t1) * HID + h * HD + e0] = r1;
        *(float2*)&g_att[(size_t)(t0 + t2) * HID + h * HD + e0] = r2;
    }
}

#define CO_SMEM (5 * 64 * PS * 4)

// ---------------- launch ----------------
extern "C" void kernel_launch(void* const* d_in, const int* in_sizes, int n_in,
                              void* d_out, int out_size)
{
    const float* x  = (const float*)d_in[0];
    const float* Wq = (const float*)d_in[1];
    const float* Wk = (const float*)d_in[2];
    const float* Wv = (const float*)d_in[3];
    const float* Wo = (const float*)d_in[4];
    float* out = (float*)d_out;

    static int attr_set = 0;
    if (!attr_set) {
        cudaFuncSetAttribute(chunk_out_kernel,
                             cudaFuncAttributeMaxDynamicSharedMemorySize, CO_SMEM);
        cudaFuncSetAttribute(gemm_qkv_kernel,
                             cudaFuncAttributeMaxDynamicSharedMemorySize, GEMM_SMEM);
        cudaFuncSetAttribute(gemm_out_kernel,
                             cudaFuncAttributeMaxDynamicSharedMemorySize, GEMM_SMEM);
        attr_set = 1;
    }

    const int TOT4 = X4 + 4 * W4;
    round_all_kernel<<<TOT4 / 256, 256>>>(x, Wq, Wk, Wv, Wo);

    dim3 gq(HID / 128, SEQ / 128, 3);
    gemm_qkv_kernel<<<gq, 256, GEMM_SMEM>>>();

    chunk_stats_kernel<<<dim3(NCHUNK, NH), 256>>>();
    chunk_scan_kernel<<<SCAN_S_BLOCKS + NH * HD / 256, 256>>>();   // 256 + 4 blocks
    chunk_out_kernel<<<dim3(NCHUNK, NH), 256, CO_SMEM>>>();

    dim3 go(HID / 128, SEQ / 128);
    gemm_out_kernel<<<go, 256, GEMM_SMEM>>>(out);
}

// round 12
// speedup vs baseline: 3.6441x; 1.0422x over previous
#include <cuda_runtime.h>
#include <math.h>
#include <stdint.h>

#define SEQ 2048
#define HID 1024
#define NH 16
#define HD 64
#define CHUNK 64
#define NCHUNK (SEQ / CHUNK)

// ---------------- scratch ----------------
__device__ float g_q[SEQ * HID];
__device__ float g_k[SEQ * HID];
__device__ float g_v[SEQ * HID];
__device__ float g_att[SEQ * HID];            // pre-rounded to tf32
__device__ float g_S[NH * NCHUNK * HD * HD];  // stored TRANSPOSED: S_store[e][d] = S[d][e]
__device__ float g_Z[NH * NCHUNK * HD];
__device__ float g_xr[SEQ * HID];
__device__ float g_wqr[HID * HID];
__device__ float g_wkr[HID * HID];
__device__ float g_wvr[HID * HID];
__device__ float g_wor[HID * HID];

__device__ __forceinline__ uint32_t f2tf32(float f) {
    uint32_t u;
    asm("cvt.rna.tf32.f32 %0, %1;" : "=r"(u) : "f"(f));
    return u;
}
__device__ __forceinline__ float rndtf32(float f) { return __uint_as_float(f2tf32(f)); }
__device__ __forceinline__ uint32_t smem_u32(const void* p) {
    uint32_t a;
    asm("{ .reg .u64 t; cvta.to.shared.u64 t, %1; cvt.u32.u64 %0, t; }" : "=r"(a) : "l"(p));
    return a;
}
__device__ __forceinline__ void split32(float f, uint32_t& hi, uint32_t& lo) {
    float fh = rndtf32(f);
    hi = __float_as_uint(fh);
    lo = f2tf32(f - fh);
}

#define MMA_TF32(c0,c1,c2,c3,a0,a1,a2,a3,b0,b1) \
    asm volatile("mma.sync.aligned.m16n8k8.row.col.f32.tf32.tf32.f32 " \
                 "{%0,%1,%2,%3}, {%4,%5,%6,%7}, {%8,%9}, {%0,%1,%2,%3};" \
                 : "+f"(c0), "+f"(c1), "+f"(c2), "+f"(c3) \
                 : "r"(a0), "r"(a1), "r"(a2), "r"(a3), "r"(b0), "r"(b1))

#define MMA3(C, ah, al, bh, bl) do { \
    MMA_TF32(C[0],C[1],C[2],C[3], ah[0],ah[1],ah[2],ah[3], bh[0],bh[1]); \
    MMA_TF32(C[0],C[1],C[2],C[3], ah[0],ah[1],ah[2],ah[3], bl[0],bl[1]); \
    MMA_TF32(C[0],C[1],C[2],C[3], al[0],al[1],al[2],al[3], bh[0],bh[1]); \
} while (0)

// ---------------- fused pre-round pass ----------------
#define X4 (SEQ * HID / 4)
#define W4 (HID * HID / 4)
__global__ __launch_bounds__(256) void round_all_kernel(
    const float* __restrict__ x, const float* __restrict__ Wq,
    const float* __restrict__ Wk, const float* __restrict__ Wv,
    const float* __restrict__ Wo)
{
    int i = blockIdx.x * 256 + threadIdx.x;
    const float4* src;
    float4* dst;
    int off;
    if (i < X4) { src = (const float4*)x; dst = (float4*)g_xr; off = i; }
    else {
        int j = i - X4;
        int seg = j >> 18;
        off = j & (W4 - 1);
        src = (const float4*)((seg == 0) ? Wq : (seg == 1) ? Wk : (seg == 2) ? Wv : Wo);
        dst = (float4*)((seg == 0) ? g_wqr : (seg == 1) ? g_wkr : (seg == 2) ? g_wvr : g_wor);
    }
    float4 v = src[off];
    v.x = rndtf32(v.x); v.y = rndtf32(v.y); v.z = rndtf32(v.z); v.w = rndtf32(v.w);
    dst[off] = v;
}

// ================= pipelined tf32 mma GEMM =================
#define GBK 32
#define GSTRIDE 36
#define NSTAGE (HID / GBK)
#define NBUF 3
#define TILE_FLOATS (128 * GSTRIDE)
#define STAGE_FLOATS (2 * TILE_FLOATS)
#define GEMM_SMEM (NBUF * STAGE_FLOATS * 4)

__device__ __forceinline__ void cpasync16(uint32_t saddr, const float* gaddr) {
    asm volatile("cp.async.cg.shared.global [%0], [%1], 16;" :: "r"(saddr), "l"(gaddr));
}

__device__ __forceinline__ void gemm_body(const float* __restrict__ A,
                                          const float* __restrict__ B,
                                          float* __restrict__ C, int act,
                                          int m0, int n0, char* smem)
{
    const uint32_t sbase = smem_u32(smem);
    const int tid = threadIdx.x;
    const int w = tid >> 5;
    const int lane = tid & 31;
    const int g = lane >> 2;
    const int l4 = lane & 3;
    const int wm = (w >> 2) * 64;
    const int wn = (w & 3) * 32;

    float c[4][4][4];
#pragma unroll
    for (int mi = 0; mi < 4; mi++)
#pragma unroll
        for (int ni = 0; ni < 4; ni++)
#pragma unroll
            for (int q = 0; q < 4; q++) c[mi][ni][q] = 0.f;

    auto prefetch = [&](int s) {
        const int b = s % NBUF;
        const uint32_t ab = sbase + (uint32_t)(b * STAGE_FLOATS) * 4;
        const uint32_t bb = ab + TILE_FLOATS * 4;
        const int k0 = s * GBK;
#pragma unroll
        for (int p = 0; p < 4; p++) {
            const int idx = tid + p * 256;
            const int r = idx >> 3, kk = (idx & 7) * 4;
            cpasync16(ab + (r * GSTRIDE + kk) * 4, &A[(size_t)(m0 + r) * HID + k0 + kk]);
            cpasync16(bb + (r * GSTRIDE + kk) * 4, &B[(size_t)(n0 + r) * HID + k0 + kk]);
        }
        asm volatile("cp.async.commit_group;" ::: "memory");
    };

    prefetch(0);
    prefetch(1);

    for (int s = 0; s < NSTAGE; s++) {
        asm volatile("cp.async.wait_group 1;" ::: "memory");
        __syncthreads();
        if (s + 2 < NSTAGE) prefetch(s + 2);

        const int b = s % NBUF;
        const float* As = (const float*)(smem) + b * STAGE_FLOATS;
        const float* Bs = As + TILE_FLOATS;

#pragma unroll
        for (int kk = 0; kk < GBK; kk += 8) {
            uint32_t a[4][4], bq[4][2];
#pragma unroll
            for (int mi = 0; mi < 4; mi++) {
                const int r = wm + mi * 16 + g;
                a[mi][0] = __float_as_uint(As[r * GSTRIDE + kk + l4]);
                a[mi][1] = __float_as_uint(As[(r + 8) * GSTRIDE + kk + l4]);
                a[mi][2] = __float_as_uint(As[r * GSTRIDE + kk + l4 + 4]);
                a[mi][3] = __float_as_uint(As[(r + 8) * GSTRIDE + kk + l4 + 4]);
            }
#pragma unroll
            for (int ni = 0; ni < 4; ni++) {
                const int r = wn + ni * 8 + g;
                bq[ni][0] = __float_as_uint(Bs[r * GSTRIDE + kk + l4]);
                bq[ni][1] = __float_as_uint(Bs[r * GSTRIDE + kk + l4 + 4]);
            }
#pragma unroll
            for (int mi = 0; mi < 4; mi++)
#pragma unroll
                for (int ni = 0; ni < 4; ni++)
                    MMA_TF32(c[mi][ni][0], c[mi][ni][1], c[mi][ni][2], c[mi][ni][3],
                             a[mi][0], a[mi][1], a[mi][2], a[mi][3],
                             bq[ni][0], bq[ni][1]);
        }
        __syncthreads();
    }
    asm volatile("cp.async.wait_group 0;" ::: "memory");

#pragma unroll
    for (int mi = 0; mi < 4; mi++) {
#pragma unroll
        for (int ri = 0; ri < 2; ri++) {
            const int m = m0 + wm + mi * 16 + g + ri * 8;
#pragma unroll
            for (int ni = 0; ni < 4; ni++) {
                float y0 = c[mi][ni][ri * 2 + 0];
                float y1 = c[mi][ni][ri * 2 + 1];
                if (act) {
                    y0 = (y0 > 0.f) ? (y0 + 1.f) : expf(y0);
                    y1 = (y1 > 0.f) ? (y1 + 1.f) : expf(y1);
                }
                const int n = n0 + wn + ni * 8 + l4 * 2;
                *(float2*)&C[(size_t)m * HID + n] = make_float2(y0, y1);
            }
        }
    }
}

extern __shared__ char sm_g[];
__global__ __launch_bounds__(256, 2) void gemm_qkv_kernel()
{
    const int z = blockIdx.z;
    const float* W = (z == 0) ? g_wqr : (z == 1) ? g_wkr : g_wvr;
    float* dst = (z == 0) ? g_q : (z == 1) ? g_k : g_v;
    gemm_body(g_xr, W, dst, z != 2, blockIdx.y * 128, blockIdx.x * 128, sm_g);
}
__global__ __launch_bounds__(256, 2) void gemm_out_kernel(float* __restrict__ out)
{
    gemm_body(g_att, g_wor, out, 0, blockIdx.y * 128, blockIdx.x * 128, sm_g);
}

// ================= Pass A: per-chunk S=K^T V (3xTF32), z=sum(k) =================
#define PS 68
__global__ __launch_bounds__(256) void chunk_stats_kernel()
{
    const int c = blockIdx.x;
    const int h = blockIdx.y;
    __shared__ float Kt[64 * PS];   // Kt[d][t]
    __shared__ float Vt[64 * PS];   // Vt[e][t]

    const int tid = threadIdx.x;
    const int t0 = c * CHUNK;

#pragma unroll
    for (int p = 0; p < 4; p++) {
        const int idx = tid + p * 256;
        const int t = idx >> 4;
        const int e4 = (idx & 15) * 4;
        float4 kv = *(const float4*)&g_k[(size_t)(t0 + t) * HID + h * HD + e4];
        Kt[(e4 + 0) * PS + t] = kv.x; Kt[(e4 + 1) * PS + t] = kv.y;
        Kt[(e4 + 2) * PS + t] = kv.z; Kt[(e4 + 3) * PS + t] = kv.w;
        float4 vv = *(const float4*)&g_v[(size_t)(t0 + t) * HID + h * HD + e4];
        Vt[(e4 + 0) * PS + t] = vv.x; Vt[(e4 + 1) * PS + t] = vv.y;
        Vt[(e4 + 2) * PS + t] = vv.z; Vt[(e4 + 3) * PS + t] = vv.w;
    }
    __syncthreads();

    if (tid < HD) {
        float z = 0.f;
        for (int t = 0; t < CHUNK; t++) z += Kt[tid * PS + t];
        g_Z[(size_t)(h * NCHUNK + c) * HD + tid] = z;
    }

    const int w = tid >> 5, lane = tid & 31;
    const int g = lane >> 2, l4 = lane & 3;
    const int wm = (w >> 1) * 16;
    const int wn = (w & 1) * 32;

    float cc[4][4];
#pragma unroll
    for (int ni = 0; ni < 4; ni++)
#pragma unroll
        for (int q = 0; q < 4; q++) cc[ni][q] = 0.f;

#pragma unroll
    for (int ks = 0; ks < 8; ks++) {
        const int k0 = ks * 8;
        uint32_t ah[4], al[4];
        split32(Vt[(wm + g) * PS + k0 + l4],         ah[0], al[0]);
        split32(Vt[(wm + g + 8) * PS + k0 + l4],     ah[1], al[1]);
        split32(Vt[(wm + g) * PS + k0 + l4 + 4],     ah[2], al[2]);
        split32(Vt[(wm + g + 8) * PS + k0 + l4 + 4], ah[3], al[3]);
#pragma unroll
        for (int ni = 0; ni < 4; ni++) {
            const int d = wn + ni * 8 + g;
            uint32_t bh[2], bl[2];
            split32(Kt[d * PS + k0 + l4],     bh[0], bl[0]);
            split32(Kt[d * PS + k0 + l4 + 4], bh[1], bl[1]);
            MMA3(cc[ni], ah, al, bh, bl);
        }
    }

    float* Sout = g_S + (size_t)(h * NCHUNK + c) * HD * HD;
#pragma unroll
    for (int ni = 0; ni < 4; ni++) {
        const int d = wn + ni * 8 + l4 * 2;
        *(float2*)&Sout[(wm + g) * HD + d]     = make_float2(cc[ni][0], cc[ni][1]);
        *(float2*)&Sout[(wm + g + 8) * HD + d] = make_float2(cc[ni][2], cc[ni][3]);
    }
}

// ---------------- Pass B: PARALLEL exclusive scan, register-batched (MLP=16) ----------------
#define SCAN_S_BLOCKS (NH * HD * HD / 256)   // 256
__global__ __launch_bounds__(256) void chunk_scan_kernel()
{
    const int bid = blockIdx.x;
    const int tid = threadIdx.x;
    if (bid < SCAN_S_BLOCKS) {
        const int gidx = bid * 256 + tid;         // 0 .. 65535
        const int h = gidx >> 12;
        const int e = gidx & 4095;
        float* p = g_S + (size_t)h * NCHUNK * HD * HD + e;
        float acc = 0.f;
#pragma unroll
        for (int b = 0; b < 2; b++) {
            float v[16];
#pragma unroll
            for (int i = 0; i < 16; i++)
                v[i] = p[(size_t)(b * 16 + i) * (HD * HD)];
#pragma unroll
            for (int i = 0; i < 16; i++) {
                p[(size_t)(b * 16 + i) * (HD * HD)] = acc;
                acc += v[i];
            }
        }
    } else {
        const int j = (bid - SCAN_S_BLOCKS) * 256 + tid;   // 0 .. 1023
        const int h = j >> 6;
        const int d = j & 63;
        float* p = g_Z + (size_t)h * NCHUNK * HD + d;
        float acc = 0.f;
#pragma unroll
        for (int b = 0; b < 2; b++) {
            float v[16];
#pragma unroll
            for (int i = 0; i < 16; i++)
                v[i] = p[(b * 16 + i) * HD];
#pragma unroll
            for (int i = 0; i < 16; i++) {
                p[(b * 16 + i) * HD] = acc;
                acc += v[i];
            }
        }
    }
}

// ================= Pass C: per-chunk output (3xTF32) =================
extern __shared__ float sm_c[];
__global__ __launch_bounds__(256) void chunk_out_kernel()
{
    const int c = blockIdx.x;
    const int h = blockIdx.y;
    float* Qs  = sm_c;                 // [64][PS] (t,d)
    float* Kb  = Qs + 64 * PS;         // [64][PS] (s,d)
    float* Spt = Kb + 64 * PS;         // [64][PS] S_store[e][d]
    float* Vt  = Spt + 64 * PS;        // [64][PS] Vt[e][s]
    float* Am  = Vt + 64 * PS;         // [64][PS] masked QK^T (t,s)
    __shared__ float zprev[HD];
    __shared__ float rowpart[HD][2];
    __shared__ float dinv[CHUNK];

    const int tid = threadIdx.x;
    const int t0 = c * CHUNK;

#pragma unroll
    for (int p = 0; p < 4; p++) {
        const int idx = tid + p * 256;
        const int r = idx >> 4;
        const int c4 = (idx & 15) * 4;
        *(float4*)&Qs[r * PS + c4] =
            *(const float4*)&g_q[(size_t)(t0 + r) * HID + h * HD + c4];
        *(float4*)&Kb[r * PS + c4] =
            *(const float4*)&g_k[(size_t)(t0 + r) * HID + h * HD + c4];
        *(float4*)&Spt[r * PS + c4] =
            *(const float4*)&g_S[(size_t)(h * NCHUNK + c) * HD * HD + r * HD + c4];
        float4 vv = *(const float4*)&g_v[(size_t)(t0 + r) * HID + h * HD + c4];
        Vt[(c4 + 0) * PS + r] = vv.x; Vt[(c4 + 1) * PS + r] = vv.y;
        Vt[(c4 + 2) * PS + r] = vv.z; Vt[(c4 + 3) * PS + r] = vv.w;
    }
    if (tid < HD) zprev[tid] = g_Z[(size_t)(h * NCHUNK + c) * HD + tid];
    __syncthreads();

    const int w = tid >> 5, lane = tid & 31;
    const int g = lane >> 2, l4 = lane & 3;
    const int wm = (w >> 1) * 16;
    const int wn = (w & 1) * 32;
    const int t1 = wm + g, t2 = wm + g + 8;

    // ---- product 1: QK^T (3xTF32) ----
    float c1[4][4];
#pragma unroll
    for (int ni = 0; ni < 4; ni++)
#pragma unroll
        for (int q = 0; q < 4; q++) c1[ni][q] = 0.f;
#pragma unroll
    for (int ks = 0; ks < 8; ks++) {
        const int k0 = ks * 8;
        uint32_t ah[4], al[4];
        split32(Qs[t1 * PS + k0 + l4],     ah[0], al[0]);
        split32(Qs[t2 * PS + k0 + l4],     ah[1], al[1]);
        split32(Qs[t1 * PS + k0 + l4 + 4], ah[2], al[2]);
        split32(Qs[t2 * PS + k0 + l4 + 4], ah[3], al[3]);
#pragma unroll
        for (int ni = 0; ni < 4; ni++) {
            const int s = wn + ni * 8 + g;
            uint32_t bh[2], bl[2];
            split32(Kb[s * PS + k0 + l4],     bh[0], bl[0]);
            split32(Kb[s * PS + k0 + l4 + 4], bh[1], bl[1]);
            MMA3(c1[ni], ah, al, bh, bl);
        }
    }
    // mask + write Am + row sums
    float tot1 = 0.f, tot2 = 0.f;
#pragma unroll
    for (int ni = 0; ni < 4; ni++) {
        const int s0 = wn + ni * 8 + 2 * l4;
        float m00 = (s0     <= t1) ? c1[ni][0] : 0.f;
        float m01 = (s0 + 1 <= t1) ? c1[ni][1] : 0.f;
        float m10 = (s0     <= t2) ? c1[ni][2] : 0.f;
        float m11 = (s0 + 1 <= t2) ? c1[ni][3] : 0.f;
        tot1 += m00 + m01;
        tot2 += m10 + m11;
        *(float2*)&Am[t1 * PS + s0] = make_float2(m00, m01);
        *(float2*)&Am[t2 * PS + s0] = make_float2(m10, m11);
    }
#pragma unroll
    for (int j = 0; j < 8; j++) {
        const int d = wn + l4 * 8 + j;
        tot1 = fmaf(Qs[t1 * PS + d], zprev[d], tot1);
        tot2 = fmaf(Qs[t2 * PS + d], zprev[d], tot2);
    }
#pragma unroll
    for (int m = 1; m < 4; m <<= 1) {
        tot1 += __shfl_xor_sync(0xffffffffu, tot1, m);
        tot2 += __shfl_xor_sync(0xffffffffu, tot2, m);
    }
    if (l4 == 0) {
        rowpart[t1][w & 1] = tot1;
        rowpart[t2][w & 1] = tot2;
    }
    __syncthreads();
    if (tid < CHUNK) dinv[tid] = 1.f / fmaxf(rowpart[tid][0] + rowpart[tid][1], 1e-6f);

    // ---- products 2+3: O = Q@Spt^T + Am@V (3xTF32) ----
    float o[4][4];
#pragma unroll
    for (int ni = 0; ni < 4; ni++)
#pragma unroll
        for (int q = 0; q < 4; q++) o[ni][q] = 0.f;
#pragma unroll
    for (int ks = 0; ks < 8; ks++) {
        const int k0 = ks * 8;
        uint32_t ah[4], al[4];
        split32(Qs[t1 * PS + k0 + l4],     ah[0], al[0]);
        split32(Qs[t2 * PS + k0 + l4],     ah[1], al[1]);
        split32(Qs[t1 * PS + k0 + l4 + 4], ah[2], al[2]);
        split32(Qs[t2 * PS + k0 + l4 + 4], ah[3], al[3]);
#pragma unroll
        for (int ni = 0; ni < 4; ni++) {
            const int e = wn + ni * 8 + g;
            uint32_t bh[2], bl[2];
            split32(Spt[e * PS + k0 + l4],     bh[0], bl[0]);
            split32(Spt[e * PS + k0 + l4 + 4], bh[1], bl[1]);
            MMA3(o[ni], ah, al, bh, bl);
        }
    }
#pragma unroll
    for (int ks = 0; ks < 8; ks++) {
        const int k0 = ks * 8;
        uint32_t ah[4], al[4];
        split32(Am[t1 * PS + k0 + l4],     ah[0], al[0]);
        split32(Am[t2 * PS + k0 + l4],     ah[1], al[1]);
        split32(Am[t1 * PS + k0 + l4 + 4], ah[2], al[2]);
        split32(Am[t2 * PS + k0 + l4 + 4], ah[3], al[3]);
#pragma unroll
        for (int ni = 0; ni < 4; ni++) {
            const int e = wn + ni * 8 + g;
            uint32_t bh[2], bl[2];
            split32(Vt[e * PS + k0 + l4],     bh[0], bl[0]);
            split32(Vt[e * PS + k0 + l4 + 4], bh[1], bl[1]);
            MMA3(o[ni], ah, al, bh, bl);
        }
    }
    __syncthreads();

    const float d1 = dinv[t1];
    const float d2 = dinv[t2];
#pragma unroll
    for (int ni = 0; ni < 4; ni++) {
        const int e0 = wn + ni * 8 + 2 * l4;
        float2 r1 = make_float2(rndtf32(o[ni][0] * d1), rndtf32(o[ni][1] * d1));
        float2 r2 = make_float2(rndtf32(o[ni][2] * d2), rndtf32(o[ni][3] * d2));
        *(float2*)&g_att[(size_t)(t0 + t1) * HID + h * HD + e0] = r1;
        *(float2*)&g_att[(size_t)(t0 + t2) * HID + h * HD + e0] = r2;
    }
}

#define CO_SMEM (5 * 64 * PS * 4)

// ---------------- launch ----------------
extern "C" void kernel_launch(void* const* d_in, const int* in_sizes, int n_in,
                              void* d_out, int out_size)
{
    const float* x  = (const float*)d_in[0];
    const float* Wq = (const float*)d_in[1];
    const float* Wk = (const float*)d_in[2];
    const float* Wv = (const float*)d_in[3];
    const float* Wo = (const float*)d_in[4];
    float* out = (float*)d_out;

    static int attr_set = 0;
    if (!attr_set) {
        cudaFuncSetAttribute(chunk_out_kernel,
                             cudaFuncAttributeMaxDynamicSharedMemorySize, CO_SMEM);
        cudaFuncSetAttribute(gemm_qkv_kernel,
                             cudaFuncAttributeMaxDynamicSharedMemorySize, GEMM_SMEM);
        cudaFuncSetAttribute(gemm_out_kernel,
                             cudaFuncAttributeMaxDynamicSharedMemorySize, GEMM_SMEM);
        attr_set = 1;
    }

    const int TOT4 = X4 + 4 * W4;
    round_all_kernel<<<TOT4 / 256, 256>>>(x, Wq, Wk, Wv, Wo);

    dim3 gq(HID / 128, SEQ / 128, 3);
    gemm_qkv_kernel<<<gq, 256, GEMM_SMEM>>>();

    chunk_stats_kernel<<<dim3(NCHUNK, NH), 256>>>();
    chunk_scan_kernel<<<SCAN_S_BLOCKS + NH * HD / 256, 256>>>();
    chunk_out_kernel<<<dim3(NCHUNK, NH), 256, CO_SMEM>>>();

    dim3 go(HID / 128, SEQ / 128);
    gemm_out_kernel<<<go, 256, GEMM_SMEM>>>(out);
}